// round 11
// baseline (speedup 1.0000x reference)
#include <cuda_runtime.h>
#include <cuda_bf16.h>
#include <stdint.h>
#include <math.h>

// ---------------- problem constants ----------------
static constexpr int cB   = 32;
static constexpr int cS   = 744;
static constexpr int cD   = 512;
static constexpr int cH   = 8;
static constexpr int cHD  = 64;
static constexpr int cL   = 4;
static constexpr int cF   = 2048;           // EXP * D
static constexpr int cBS  = cB * cS;        // 23808 = 186 * 128
static constexpr int cBSH = cBS * cH;       // 190464

// ---------------- scratch (device globals; no allocations allowed) ----------
__device__ float g_h [cBS * cD];
__device__ float g_q [cBS * cD];
__device__ float g_k [cBS * cD];
__device__ float g_v [cBS * cD];
__device__ float g_t [cBS * cD];
__device__ float g_n1[cBS * cD];
__device__ float g_t2[cBS * cD];
// bf16 hi/lo split buffers
__device__ __nv_bfloat16 g_ah[(size_t)cBS * cD];   // activation split (o, then n1)
__device__ __nv_bfloat16 g_al[(size_t)cBS * cD];
__device__ __nv_bfloat16 g_fh[(size_t)cBS * cF];   // f1 split
__device__ __nv_bfloat16 g_fl[(size_t)cBS * cF];
__device__ __nv_bfloat16 g_wh[(size_t)cD * cF];    // weight split (reused per GEMM)
__device__ __nv_bfloat16 g_wl[(size_t)cD * cF];

// =====================================================================
// helpers
// =====================================================================
__device__ __forceinline__ uint32_t smem_u32(const void* p) {
    uint32_t a;
    asm("{ .reg .u64 t; cvta.to.shared.u64 t, %1; cvt.u32.u64 %0, t; }" : "=r"(a) : "l"(p));
    return a;
}
__device__ __forceinline__ void ldsm4(uint32_t* r, uint32_t a) {
    asm volatile("ldmatrix.sync.aligned.m8n8.x4.shared.b16 {%0,%1,%2,%3}, [%4];"
                 : "=r"(r[0]), "=r"(r[1]), "=r"(r[2]), "=r"(r[3]) : "r"(a));
}
__device__ __forceinline__ void mma16816(float* c, const uint32_t* a,
                                         uint32_t b0, uint32_t b1) {
    asm volatile(
        "mma.sync.aligned.m16n8k16.row.col.f32.bf16.bf16.f32 "
        "{%0,%1,%2,%3}, {%4,%5,%6,%7}, {%8,%9}, {%0,%1,%2,%3};"
        : "+f"(c[0]), "+f"(c[1]), "+f"(c[2]), "+f"(c[3])
        : "r"(a[0]), "r"(a[1]), "r"(a[2]), "r"(a[3]), "r"(b0), "r"(b1));
}
__device__ __forceinline__ void cpa16(uint32_t dst, const void* src) {
    asm volatile("cp.async.cg.shared.global [%0], [%1], 16;" :: "r"(dst), "l"(src));
}
__device__ __forceinline__ void cpa_commit() {
    asm volatile("cp.async.commit_group;" ::: "memory");
}
__device__ __forceinline__ void cpa_wait1() {
    asm volatile("cp.async.wait_group 1;" ::: "memory");
}
__device__ __forceinline__ uint32_t pack_split(float x, float y,
                                               __nv_bfloat16& lx, __nv_bfloat16& ly) {
    __nv_bfloat16 hx = __float2bfloat16_rn(x);
    __nv_bfloat16 hy = __float2bfloat16_rn(y);
    lx = __float2bfloat16_rn(x - __bfloat162float(hx));
    ly = __float2bfloat16_rn(y - __bfloat162float(hy));
    __nv_bfloat162 t(hx, hy);
    return *reinterpret_cast<uint32_t*>(&t);
}

// ---------------- fp32 -> bf16 hi/lo split (weights) ----------------
__global__ void k_split(const float* __restrict__ s, __nv_bfloat16* __restrict__ hi,
                        __nv_bfloat16* __restrict__ lo, int n4)
{
    int i = blockIdx.x * blockDim.x + threadIdx.x;
    if (i >= n4) return;
    float4 v = reinterpret_cast<const float4*>(s)[i];
    __nv_bfloat16 l0, l1, l2, l3;
    uint32_t h01 = pack_split(v.x, v.y, l0, l1);
    uint32_t h23 = pack_split(v.z, v.w, l2, l3);
    __nv_bfloat162 lo01(l0, l1), lo23(l2, l3);
    reinterpret_cast<uint2*>(hi)[i] = make_uint2(h01, h23);
    reinterpret_cast<uint2*>(lo)[i] = make_uint2(*reinterpret_cast<uint32_t*>(&lo01),
                                                *reinterpret_cast<uint32_t*>(&lo23));
}

// =====================================================================
// bf16x3 pipelined tensor GEMM (cp.async, 3 stages)
// C = A[M,K] @ B[N,K]^T + bias, A/B given as pre-split bf16 hi/lo.
// MODE 0: fp32 out + residual.  MODE 1: relu, split bf16 out (Ch/Cl).
// Tile 128x128, K-block 32, 256 threads, warp grid 2(m) x 4(n).
// =====================================================================
static constexpr int SROW    = 40;                    // bf16 per smem row (80 B)
static constexpr int ARR_B   = 128 * SROW * 2;        // 10240 B per array
static constexpr int STAGE_B = 4 * ARR_B;             // 40960 B per stage
static constexpr int NST     = 3;
static constexpr int GEMM_SMEM = NST * STAGE_B;       // 122880 B

template<int MODE>
__global__ __launch_bounds__(256, 1) void mma_gemm(
    const __nv_bfloat16* __restrict__ Ahg, const __nv_bfloat16* __restrict__ Alg,
    const __nv_bfloat16* __restrict__ Bhg, const __nv_bfloat16* __restrict__ Blg,
    const float* __restrict__ bias, const float* __restrict__ resid,
    float* __restrict__ C, __nv_bfloat16* __restrict__ Ch, __nv_bfloat16* __restrict__ Cl,
    int M, int N, int K)
{
    extern __shared__ __align__(128) char smem[];
    const uint32_t sb0 = smem_u32(smem);

    const int tid  = threadIdx.x;
    const int w    = tid >> 5, lane = tid & 31;
    const int m0   = blockIdx.y * 128, n0 = blockIdx.x * 128;
    const int wm   = (w & 1) * 64;
    const int wn   = (w >> 1) * 32;

    const __nv_bfloat16* srcs[4] = {
        Ahg + (size_t)m0 * K, Alg + (size_t)m0 * K,
        Bhg + (size_t)n0 * K, Blg + (size_t)n0 * K };

    // cp.async loader: 8 x 16B per thread per stage
    const int l_row = tid >> 2, l_ch = tid & 3;
    auto load_stage = [&](int s) {
        uint32_t base = sb0 + (uint32_t)((s % NST) * STAGE_B);
        #pragma unroll
        for (int u = 0; u < 8; u++) {
            int arr = u >> 1;
            int idx = tid + (u & 1) * 256;
            int row = idx >> 2, ch = idx & 3;
            cpa16(base + (uint32_t)(arr * ARR_B + row * 80 + ch * 16),
                  srcs[arr] + (size_t)row * K + s * 32 + ch * 8);
        }
        (void)l_row; (void)l_ch;
    };

    // ldmatrix per-lane offsets (bytes)
    const uint32_t a_lane = (uint32_t)((wm + (lane & 15)) * 80 + (lane >> 4) * 16);
    const uint32_t b_lane = (uint32_t)(
        (wn + ((lane >> 4) & 1) * 8 + (lane & 7)) * 80 + ((lane >> 3) & 1) * 16);

    float acc[4][4][4] = {};
    const int NK = K >> 5;

    load_stage(0); cpa_commit();
    load_stage(1); cpa_commit();

    for (int kt = 0; kt < NK; kt++) {
        cpa_wait1();
        __syncthreads();
        if (kt + 2 < NK) load_stage(kt + 2);
        cpa_commit();

        const uint32_t sk = sb0 + (uint32_t)((kt % NST) * STAGE_B);
        const uint32_t aAh = sk, aAl = sk + ARR_B, aBh = sk + 2 * ARR_B, aBl = sk + 3 * ARR_B;

        #pragma unroll
        for (int kk = 0; kk < 2; kk++) {
            const uint32_t kof = (uint32_t)(kk * 32);
            uint32_t ah[4][4], al[4][4];
            #pragma unroll
            for (int mi = 0; mi < 4; mi++) {
                uint32_t off = a_lane + (uint32_t)(mi * 16 * 80) + kof;
                ldsm4(ah[mi], aAh + off);
                ldsm4(al[mi], aAl + off);
            }
            uint32_t bh[2][4], bl[2][4];
            #pragma unroll
            for (int j = 0; j < 2; j++) {
                uint32_t off = b_lane + (uint32_t)(j * 16 * 80) + kof;
                ldsm4(bh[j], aBh + off);
                ldsm4(bl[j], aBl + off);
            }
            #pragma unroll
            for (int mi = 0; mi < 4; mi++) {
                #pragma unroll
                for (int ni = 0; ni < 4; ni++) {
                    int j = ni >> 1, s = (ni & 1) * 2;
                    mma16816(acc[mi][ni], ah[mi], bh[j][s], bh[j][s + 1]);
                    mma16816(acc[mi][ni], ah[mi], bl[j][s], bl[j][s + 1]);
                    mma16816(acc[mi][ni], al[mi], bh[j][s], bh[j][s + 1]);
                }
            }
        }
    }

    // epilogue
    const int rbase = m0 + wm + (lane >> 2);
    const int cgrp  = (lane & 3) * 2;
    #pragma unroll
    for (int mi = 0; mi < 4; mi++) {
        int r1 = rbase + mi * 16;
        int r2 = r1 + 8;
        #pragma unroll
        for (int ni = 0; ni < 4; ni++) {
            int col = n0 + wn + ni * 8 + cgrp;
            float2 bv = *reinterpret_cast<const float2*>(bias + col);
            float2 v1 = make_float2(acc[mi][ni][0] + bv.x, acc[mi][ni][1] + bv.y);
            float2 v2 = make_float2(acc[mi][ni][2] + bv.x, acc[mi][ni][3] + bv.y);
            if (MODE == 0) {
                float2 q1 = *reinterpret_cast<const float2*>(resid + (size_t)r1 * N + col);
                float2 q2 = *reinterpret_cast<const float2*>(resid + (size_t)r2 * N + col);
                v1.x += q1.x; v1.y += q1.y; v2.x += q2.x; v2.y += q2.y;
                *reinterpret_cast<float2*>(C + (size_t)r1 * N + col) = v1;
                *reinterpret_cast<float2*>(C + (size_t)r2 * N + col) = v2;
            } else {
                v1.x = fmaxf(v1.x, 0.f); v1.y = fmaxf(v1.y, 0.f);
                v2.x = fmaxf(v2.x, 0.f); v2.y = fmaxf(v2.y, 0.f);
                __nv_bfloat16 lx, ly;
                uint32_t h1 = pack_split(v1.x, v1.y, lx, ly);
                __nv_bfloat162 lo1(lx, ly);
                *reinterpret_cast<uint32_t*>(Ch + (size_t)r1 * N + col) = h1;
                *reinterpret_cast<uint32_t*>(Cl + (size_t)r1 * N + col) =
                    *reinterpret_cast<uint32_t*>(&lo1);
                uint32_t h2 = pack_split(v2.x, v2.y, lx, ly);
                __nv_bfloat162 lo2(lx, ly);
                *reinterpret_cast<uint32_t*>(Ch + (size_t)r2 * N + col) = h2;
                *reinterpret_cast<uint32_t*>(Cl + (size_t)r2 * N + col) =
                    *reinterpret_cast<uint32_t*>(&lo2);
            }
        }
    }
}

// ---------------- embedding + positional encoding ----------------
__global__ void k_embed(const int* __restrict__ x, const float* __restrict__ emb,
                        const float* __restrict__ pe, float* __restrict__ h)
{
    int i = blockIdx.x * blockDim.x + threadIdx.x;
    const int n4 = cBS * cD / 4;
    if (i >= n4) return;
    int d4 = i & (cD / 4 - 1);
    int bs = i >> 7;
    int s  = bs % cS;
    int tok = x[bs];
    float4 e = reinterpret_cast<const float4*>(emb)[tok * (cD / 4) + d4];
    float4 p = reinterpret_cast<const float4*>(pe)[s * (cD / 4) + d4];
    const float sc = 22.62741699796952f;    // sqrt(512)
    float4 r;
    r.x = e.x * sc + p.x; r.y = e.y * sc + p.y;
    r.z = e.z * sc + p.z; r.w = e.w * sc + p.w;
    reinterpret_cast<float4*>(h)[i] = r;
}

// ---------------- fused QKV: [BSH,64] @ W^T for W in {Wq,Wk,Wv} --------------
__global__ __launch_bounds__(256) void k_qkv(
    const float* __restrict__ h,
    const float* __restrict__ Wq, const float* __restrict__ Wk, const float* __restrict__ Wv,
    float* __restrict__ q, float* __restrict__ k, float* __restrict__ v)
{
    __shared__ __align__(16) float xs[64][68];
    __shared__ __align__(16) float ws[64][64];
    int tid = threadIdx.x;
    int tx = tid & 15, ty = tid >> 4;
    int row0 = blockIdx.x * 64;

    #pragma unroll
    for (int u = 0; u < 4; u++) {
        int f = tid + u * 256;
        int r = f >> 4, c4 = f & 15;
        float4 val = reinterpret_cast<const float4*>(h + (size_t)(row0 + r) * 64)[c4];
        *reinterpret_cast<float4*>(&xs[r][c4 * 4]) = val;
    }

    const float* Wm[3] = {Wq, Wk, Wv};
    float*       Om[3] = {q,  k,  v };
    #pragma unroll
    for (int m = 0; m < 3; m++) {
        __syncthreads();
        #pragma unroll
        for (int u = 0; u < 4; u++) {
            int f = tid + u * 256;
            int e = f >> 4, c4 = f & 15;
            float4 w4 = reinterpret_cast<const float4*>(Wm[m] + e * 64)[c4];
            ws[c4 * 4 + 0][e] = w4.x;
            ws[c4 * 4 + 1][e] = w4.y;
            ws[c4 * 4 + 2][e] = w4.z;
            ws[c4 * 4 + 3][e] = w4.w;
        }
        __syncthreads();
        float acc[4][4] = {};
        #pragma unroll
        for (int d = 0; d < 64; d++) {
            float a0 = xs[ty * 4 + 0][d];
            float a1 = xs[ty * 4 + 1][d];
            float a2 = xs[ty * 4 + 2][d];
            float a3 = xs[ty * 4 + 3][d];
            float4 b4 = *reinterpret_cast<const float4*>(&ws[d][tx * 4]);
            acc[0][0] += a0 * b4.x; acc[0][1] += a0 * b4.y; acc[0][2] += a0 * b4.z; acc[0][3] += a0 * b4.w;
            acc[1][0] += a1 * b4.x; acc[1][1] += a1 * b4.y; acc[1][2] += a1 * b4.z; acc[1][3] += a1 * b4.w;
            acc[2][0] += a2 * b4.x; acc[2][1] += a2 * b4.y; acc[2][2] += a2 * b4.z; acc[2][3] += a2 * b4.w;
            acc[3][0] += a3 * b4.x; acc[3][1] += a3 * b4.y; acc[3][2] += a3 * b4.z; acc[3][3] += a3 * b4.w;
        }
        #pragma unroll
        for (int i = 0; i < 4; i++) {
            float4 r4 = make_float4(acc[i][0], acc[i][1], acc[i][2], acc[i][3]);
            *reinterpret_cast<float4*>(Om[m] + (size_t)(row0 + ty * 4 + i) * 64 + tx * 4) = r4;
        }
    }
}

// ---------------- flash attention (fp32, 64x64 tiles, online softmax) --------
// Epilogue writes split bf16 hi/lo (feeds Wo GEMM directly).
static constexpr int ATTN_SMEM_BYTES = (4 * 64 * 68 + 3 * 64) * 4;   // 70400 B

__global__ __launch_bounds__(256) void k_attn(
    const float* __restrict__ qg, const float* __restrict__ kg,
    const float* __restrict__ vg,
    __nv_bfloat16* __restrict__ oh, __nv_bfloat16* __restrict__ ol)
{
    extern __shared__ __align__(16) float sm[];
    float* qs  = sm;
    float* kst = sm + 64 * 68;
    float* vs  = sm + 2 * 64 * 68;
    float* ps  = sm + 3 * 64 * 68;
    float* m_s = sm + 4 * 64 * 68;
    float* l_s = m_s + 64;
    float* a_s = l_s + 64;

    int tid = threadIdx.x;
    int tx = tid & 15, ty = tid >> 4;
    int s0 = blockIdx.x * 64;
    int bh = blockIdx.y;
    int b = bh >> 3, hh = bh & 7;
    const size_t base = (size_t)b * cS * cD + hh * 64;

    #pragma unroll
    for (int u = 0; u < 4; u++) {
        int f = tid + u * 256;
        int r = f >> 4, c4 = f & 15;
        float4 val = make_float4(0.f, 0.f, 0.f, 0.f);
        if (s0 + r < cS)
            val = *reinterpret_cast<const float4*>(qg + base + (size_t)(s0 + r) * cD + c4 * 4);
        *reinterpret_cast<float4*>(&qs[r * 68 + c4 * 4]) = val;
    }
    if (tid < 64) { m_s[tid] = -1e30f; l_s[tid] = 0.f; }

    float acc[4][4] = {};

    for (int kb = 0; kb < cS; kb += 64) {
        __syncthreads();
        #pragma unroll
        for (int u = 0; u < 4; u++) {
            int f = tid + u * 256;
            int r = f >> 4, c4 = f & 15;
            float4 kv = make_float4(0.f, 0.f, 0.f, 0.f);
            float4 vv = make_float4(0.f, 0.f, 0.f, 0.f);
            if (kb + r < cS) {
                kv = *reinterpret_cast<const float4*>(kg + base + (size_t)(kb + r) * cD + c4 * 4);
                vv = *reinterpret_cast<const float4*>(vg + base + (size_t)(kb + r) * cD + c4 * 4);
            }
            kst[(c4 * 4 + 0) * 68 + r] = kv.x;
            kst[(c4 * 4 + 1) * 68 + r] = kv.y;
            kst[(c4 * 4 + 2) * 68 + r] = kv.z;
            kst[(c4 * 4 + 3) * 68 + r] = kv.w;
            *reinterpret_cast<float4*>(&vs[r * 68 + c4 * 4]) = vv;
        }
        __syncthreads();

        float scv[4][4] = {};
        #pragma unroll
        for (int d = 0; d < 64; d++) {
            float a0 = qs[(ty * 4 + 0) * 68 + d];
            float a1 = qs[(ty * 4 + 1) * 68 + d];
            float a2 = qs[(ty * 4 + 2) * 68 + d];
            float a3 = qs[(ty * 4 + 3) * 68 + d];
            float4 b4 = *reinterpret_cast<const float4*>(&kst[d * 68 + tx * 4]);
            scv[0][0] += a0 * b4.x; scv[0][1] += a0 * b4.y; scv[0][2] += a0 * b4.z; scv[0][3] += a0 * b4.w;
            scv[1][0] += a1 * b4.x; scv[1][1] += a1 * b4.y; scv[1][2] += a1 * b4.z; scv[1][3] += a1 * b4.w;
            scv[2][0] += a2 * b4.x; scv[2][1] += a2 * b4.y; scv[2][2] += a2 * b4.z; scv[2][3] += a2 * b4.w;
            scv[3][0] += a3 * b4.x; scv[3][1] += a3 * b4.y; scv[3][2] += a3 * b4.z; scv[3][3] += a3 * b4.w;
        }
        #pragma unroll
        for (int i = 0; i < 4; i++) {
            int c = kb + tx * 4;
            float4 r4;
            r4.x = (c + 0 < cS) ? scv[i][0] * 0.125f : -1e30f;
            r4.y = (c + 1 < cS) ? scv[i][1] * 0.125f : -1e30f;
            r4.z = (c + 2 < cS) ? scv[i][2] * 0.125f : -1e30f;
            r4.w = (c + 3 < cS) ? scv[i][3] * 0.125f : -1e30f;
            *reinterpret_cast<float4*>(&ps[(ty * 4 + i) * 68 + tx * 4]) = r4;
        }
        __syncthreads();

        {
            int row = tid >> 2, qt = tid & 3;
            float* pr = &ps[row * 68 + qt * 16];
            float lm = -1e30f;
            #pragma unroll
            for (int c = 0; c < 16; c++) lm = fmaxf(lm, pr[c]);
            lm = fmaxf(lm, __shfl_xor_sync(0xffffffffu, lm, 1));
            lm = fmaxf(lm, __shfl_xor_sync(0xffffffffu, lm, 2));
            float m_old = m_s[row];
            float m_new = fmaxf(m_old, lm);
            float alpha = __expf(m_old - m_new);
            float lsum = 0.f;
            #pragma unroll
            for (int c = 0; c < 16; c++) {
                float p = __expf(pr[c] - m_new);
                pr[c] = p;
                lsum += p;
            }
            lsum += __shfl_xor_sync(0xffffffffu, lsum, 1);
            lsum += __shfl_xor_sync(0xffffffffu, lsum, 2);
            if (qt == 0) {
                m_s[row] = m_new;
                l_s[row] = l_s[row] * alpha + lsum;
                a_s[row] = alpha;
            }
        }
        __syncthreads();

        #pragma unroll
        for (int i = 0; i < 4; i++) {
            float al = a_s[ty * 4 + i];
            acc[i][0] *= al; acc[i][1] *= al; acc[i][2] *= al; acc[i][3] *= al;
        }
        #pragma unroll
        for (int c = 0; c < 64; c++) {
            float4 v4 = *reinterpret_cast<const float4*>(&vs[c * 68 + tx * 4]);
            float p0 = ps[(ty * 4 + 0) * 68 + c];
            float p1 = ps[(ty * 4 + 1) * 68 + c];
            float p2 = ps[(ty * 4 + 2) * 68 + c];
            float p3 = ps[(ty * 4 + 3) * 68 + c];
            acc[0][0] += p0 * v4.x; acc[0][1] += p0 * v4.y; acc[0][2] += p0 * v4.z; acc[0][3] += p0 * v4.w;
            acc[1][0] += p1 * v4.x; acc[1][1] += p1 * v4.y; acc[1][2] += p1 * v4.z; acc[1][3] += p1 * v4.w;
            acc[2][0] += p2 * v4.x; acc[2][1] += p2 * v4.y; acc[2][2] += p2 * v4.z; acc[2][3] += p2 * v4.w;
            acc[3][0] += p3 * v4.x; acc[3][1] += p3 * v4.y; acc[3][2] += p3 * v4.z; acc[3][3] += p3 * v4.w;
        }
    }

    #pragma unroll
    for (int i = 0; i < 4; i++) {
        int s = s0 + ty * 4 + i;
        if (s < cS) {
            float inv = 1.f / l_s[ty * 4 + i];
            float r0 = acc[i][0] * inv, r1 = acc[i][1] * inv;
            float r2 = acc[i][2] * inv, r3 = acc[i][3] * inv;
            size_t off = base + (size_t)s * cD + tx * 4;
            __nv_bfloat16 lx, ly;
            uint32_t h01 = pack_split(r0, r1, lx, ly);
            __nv_bfloat162 lo01(lx, ly);
            uint32_t h23 = pack_split(r2, r3, lx, ly);
            __nv_bfloat162 lo23(lx, ly);
            *reinterpret_cast<uint2*>(oh + off) =
                make_uint2(h01, h23);
            *reinterpret_cast<uint2*>(ol + off) =
                make_uint2(*reinterpret_cast<uint32_t*>(&lo01),
                           *reinterpret_cast<uint32_t*>(&lo23));
        }
    }
}

// ---------------- LayerNorm over rows of 512 (optional split output) --------
template<bool SPLIT>
__global__ void k_ln(const float* __restrict__ x, const float* __restrict__ w,
                     const float* __restrict__ bb, float* __restrict__ out,
                     __nv_bfloat16* __restrict__ oh, __nv_bfloat16* __restrict__ ol)
{
    __shared__ float red[4];
    int row = blockIdx.x;
    int t = threadIdx.x;
    const float4 v = reinterpret_cast<const float4*>(x + (size_t)row * cD)[t];
    float s = v.x + v.y + v.z + v.w;
    #pragma unroll
    for (int o = 16; o > 0; o >>= 1) s += __shfl_xor_sync(0xffffffffu, s, o);
    if ((t & 31) == 0) red[t >> 5] = s;
    __syncthreads();
    float mean = (red[0] + red[1] + red[2] + red[3]) * (1.0f / cD);
    float dx = v.x - mean, dy = v.y - mean, dz = v.z - mean, dw = v.w - mean;
    float s2 = dx * dx + dy * dy + dz * dz + dw * dw;
    #pragma unroll
    for (int o = 16; o > 0; o >>= 1) s2 += __shfl_xor_sync(0xffffffffu, s2, o);
    __syncthreads();
    if ((t & 31) == 0) red[t >> 5] = s2;
    __syncthreads();
    float var = (red[0] + red[1] + red[2] + red[3]) * (1.0f / cD);
    float inv = rsqrtf(var + 1e-5f);
    float4 wv = reinterpret_cast<const float4*>(w)[t];
    float4 bv = reinterpret_cast<const float4*>(bb)[t];
    float4 r4;
    r4.x = dx * inv * wv.x + bv.x;
    r4.y = dy * inv * wv.y + bv.y;
    r4.z = dz * inv * wv.z + bv.z;
    r4.w = dw * inv * wv.w + bv.w;
    reinterpret_cast<float4*>(out + (size_t)row * cD)[t] = r4;
    if (SPLIT) {
        size_t off = (size_t)row * cD + t * 4;
        __nv_bfloat16 lx, ly;
        uint32_t h01 = pack_split(r4.x, r4.y, lx, ly);
        __nv_bfloat162 lo01(lx, ly);
        uint32_t h23 = pack_split(r4.z, r4.w, lx, ly);
        __nv_bfloat162 lo23(lx, ly);
        *reinterpret_cast<uint2*>(oh + off) = make_uint2(h01, h23);
        *reinterpret_cast<uint2*>(ol + off) =
            make_uint2(*reinterpret_cast<uint32_t*>(&lo01),
                       *reinterpret_cast<uint32_t*>(&lo23));
    }
}

// ---------------- driver ----------------
extern "C" void kernel_launch(void* const* d_in, const int* in_sizes, int n_in,
                              void* d_out, int out_size)
{
    const int*   x    = (const int*)  d_in[0];
    const float* emb  = (const float*)d_in[1];
    const float* pe   = (const float*)d_in[2];
    const float* Wq   = (const float*)d_in[3];
    const float* Wk   = (const float*)d_in[4];
    const float* Wv   = (const float*)d_in[5];
    const float* Wo   = (const float*)d_in[6];
    const float* bo   = (const float*)d_in[7];
    const float* ln1w = (const float*)d_in[8];
    const float* ln1b = (const float*)d_in[9];
    const float* W1   = (const float*)d_in[10];
    const float* b1   = (const float*)d_in[11];
    const float* W2   = (const float*)d_in[12];
    const float* b2   = (const float*)d_in[13];
    const float* ln2w = (const float*)d_in[14];
    const float* ln2b = (const float*)d_in[15];
    float* out = (float*)d_out;

    float *h, *q, *k, *v, *t, *n1, *t2;
    __nv_bfloat16 *ah, *al, *fh, *fl, *wh, *wl;
    cudaGetSymbolAddress((void**)&h,  g_h);
    cudaGetSymbolAddress((void**)&q,  g_q);
    cudaGetSymbolAddress((void**)&k,  g_k);
    cudaGetSymbolAddress((void**)&v,  g_v);
    cudaGetSymbolAddress((void**)&t,  g_t);
    cudaGetSymbolAddress((void**)&n1, g_n1);
    cudaGetSymbolAddress((void**)&t2, g_t2);
    cudaGetSymbolAddress((void**)&ah, g_ah);
    cudaGetSymbolAddress((void**)&al, g_al);
    cudaGetSymbolAddress((void**)&fh, g_fh);
    cudaGetSymbolAddress((void**)&fl, g_fl);
    cudaGetSymbolAddress((void**)&wh, g_wh);
    cudaGetSymbolAddress((void**)&wl, g_wl);

    cudaFuncSetAttribute(k_attn, cudaFuncAttributeMaxDynamicSharedMemorySize, ATTN_SMEM_BYTES);
    cudaFuncSetAttribute(mma_gemm<0>, cudaFuncAttributeMaxDynamicSharedMemorySize, GEMM_SMEM);
    cudaFuncSetAttribute(mma_gemm<1>, cudaFuncAttributeMaxDynamicSharedMemorySize, GEMM_SMEM);

    k_embed<<<(cBS * cD / 4 + 255) / 256, 256>>>(x, emb, pe, h);

    for (int l = 0; l < cL; l++) {
        k_qkv<<<cBSH / 64, 256>>>(h, Wq + l * cHD * cHD, Wk + l * cHD * cHD,
                                  Wv + l * cHD * cHD, q, k, v);
        // attention -> o (split bf16 in ah/al)
        k_attn<<<dim3((cS + 63) / 64, cB * cH), 256, ATTN_SMEM_BYTES>>>(q, k, v, ah, al);

        // t = o @ Wo^T + bo + h
        k_split<<<(cD * cD / 4 + 255) / 256, 256>>>(Wo + (size_t)l * cD * cD, wh, wl, cD * cD / 4);
        mma_gemm<0><<<dim3(cD / 128, cBS / 128), 256, GEMM_SMEM>>>(
            ah, al, wh, wl, bo + l * cD, h, t, nullptr, nullptr, cBS, cD, cD);
        k_ln<true><<<cBS, 128>>>(t, ln1w + l * cD, ln1b + l * cD, n1, ah, al);

        // f1 = relu(n1 @ W1^T + b1)  (split bf16 out)
        k_split<<<(cF * cD / 4 + 255) / 256, 256>>>(W1 + (size_t)l * cF * cD, wh, wl, cF * cD / 4);
        mma_gemm<1><<<dim3(cF / 128, cBS / 128), 256, GEMM_SMEM>>>(
            ah, al, wh, wl, b1 + l * cF, nullptr, nullptr, fh, fl, cBS, cF, cD);

        // t2 = f1 @ W2^T + b2 + n1
        k_split<<<(cF * cD / 4 + 255) / 256, 256>>>(W2 + (size_t)l * cD * cF, wh, wl, cF * cD / 4);
        mma_gemm<0><<<dim3(cD / 128, cBS / 128), 256, GEMM_SMEM>>>(
            fh, fl, wh, wl, b2 + l * cD, n1, t2, nullptr, nullptr, cBS, cD, cF);

        k_ln<false><<<cBS, 128>>>(t2, ln2w + l * cD, ln2b + l * cD,
                                  (l == cL - 1) ? out : h, nullptr, nullptr);
    }
}

// round 15
// speedup vs baseline: 1.1561x; 1.1561x over previous
#include <cuda_runtime.h>
#include <cuda_bf16.h>
#include <stdint.h>
#include <math.h>

// ---------------- problem constants ----------------
static constexpr int cB   = 32;
static constexpr int cS   = 744;
static constexpr int cD   = 512;
static constexpr int cH   = 8;
static constexpr int cHD  = 64;
static constexpr int cL   = 4;
static constexpr int cF   = 2048;           // EXP * D
static constexpr int cBS  = cB * cS;        // 23808 = 186 * 128
static constexpr int cBSH = cBS * cH;       // 190464

// ---------------- scratch (device globals; no allocations allowed) ----------
__device__ float g_h [cBS * cD];
__device__ float g_v [cBS * cD];
__device__ float g_t [cBS * cD];
__device__ float g_n1[cBS * cD];
__device__ float g_t2[cBS * cD];
// bf16 hi/lo split buffers
__device__ __nv_bfloat16 g_qh[(size_t)cBS * cD];
__device__ __nv_bfloat16 g_ql[(size_t)cBS * cD];
__device__ __nv_bfloat16 g_kh[(size_t)cBS * cD];
__device__ __nv_bfloat16 g_kl[(size_t)cBS * cD];
__device__ __nv_bfloat16 g_ah[(size_t)cBS * cD];   // activation split (o, then n1)
__device__ __nv_bfloat16 g_al[(size_t)cBS * cD];
__device__ __nv_bfloat16 g_fh[(size_t)cBS * cF];   // f1 split
__device__ __nv_bfloat16 g_fl[(size_t)cBS * cF];
__device__ __nv_bfloat16 g_wh[(size_t)cD * cF];    // weight split (reused per GEMM)
__device__ __nv_bfloat16 g_wl[(size_t)cD * cF];

// =====================================================================
// helpers
// =====================================================================
__device__ __forceinline__ uint32_t smem_u32(const void* p) {
    uint32_t a;
    asm("{ .reg .u64 t; cvta.to.shared.u64 t, %1; cvt.u32.u64 %0, t; }" : "=r"(a) : "l"(p));
    return a;
}
__device__ __forceinline__ void ldsm4(uint32_t* r, uint32_t a) {
    asm volatile("ldmatrix.sync.aligned.m8n8.x4.shared.b16 {%0,%1,%2,%3}, [%4];"
                 : "=r"(r[0]), "=r"(r[1]), "=r"(r[2]), "=r"(r[3]) : "r"(a));
}
__device__ __forceinline__ void mma16816(float* c, const uint32_t* a,
                                         uint32_t b0, uint32_t b1) {
    asm volatile(
        "mma.sync.aligned.m16n8k16.row.col.f32.bf16.bf16.f32 "
        "{%0,%1,%2,%3}, {%4,%5,%6,%7}, {%8,%9}, {%0,%1,%2,%3};"
        : "+f"(c[0]), "+f"(c[1]), "+f"(c[2]), "+f"(c[3])
        : "r"(a[0]), "r"(a[1]), "r"(a[2]), "r"(a[3]), "r"(b0), "r"(b1));
}
__device__ __forceinline__ void cpa16(uint32_t dst, const void* src) {
    asm volatile("cp.async.cg.shared.global [%0], [%1], 16;" :: "r"(dst), "l"(src));
}
__device__ __forceinline__ void cpa_commit() {
    asm volatile("cp.async.commit_group;" ::: "memory");
}
__device__ __forceinline__ void cpa_wait1() {
    asm volatile("cp.async.wait_group 1;" ::: "memory");
}
__device__ __forceinline__ uint32_t pack_split(float x, float y,
                                               __nv_bfloat16& lx, __nv_bfloat16& ly) {
    __nv_bfloat16 hx = __float2bfloat16_rn(x);
    __nv_bfloat16 hy = __float2bfloat16_rn(y);
    lx = __float2bfloat16_rn(x - __bfloat162float(hx));
    ly = __float2bfloat16_rn(y - __bfloat162float(hy));
    __nv_bfloat162 t(hx, hy);
    return *reinterpret_cast<uint32_t*>(&t);
}

// ---------------- fp32 -> bf16 hi/lo split (weights) ----------------
__global__ void k_split(const float* __restrict__ s, __nv_bfloat16* __restrict__ hi,
                        __nv_bfloat16* __restrict__ lo, int n4)
{
    int i = blockIdx.x * blockDim.x + threadIdx.x;
    if (i >= n4) return;
    float4 v = reinterpret_cast<const float4*>(s)[i];
    __nv_bfloat16 l0, l1, l2, l3;
    uint32_t h01 = pack_split(v.x, v.y, l0, l1);
    uint32_t h23 = pack_split(v.z, v.w, l2, l3);
    __nv_bfloat162 lo01(l0, l1), lo23(l2, l3);
    reinterpret_cast<uint2*>(hi)[i] = make_uint2(h01, h23);
    reinterpret_cast<uint2*>(lo)[i] = make_uint2(*reinterpret_cast<uint32_t*>(&lo01),
                                                *reinterpret_cast<uint32_t*>(&lo23));
}

// =====================================================================
// bf16x3 pipelined tensor GEMM (cp.async, 3 stages, 512 threads, 16 warps)
// C = A[M,K] @ B[N,K]^T + bias, A/B given as pre-split bf16 hi/lo.
// MODE 0: fp32 out + residual.  MODE 1: relu, split bf16 out (Ch/Cl).
// Tile 128x128, K-block 32, warp grid 4(m) x 4(n), warp tile 32x32.
// =====================================================================
static constexpr int ARR_B   = 128 * 80;              // 10240 B per array
static constexpr int STAGE_B = 4 * ARR_B;             // 40960 B per stage
static constexpr int NST     = 3;
static constexpr int GEMM_SMEM = NST * STAGE_B;       // 122880 B

template<int MODE>
__global__ __launch_bounds__(512, 1) void mma_gemm(
    const __nv_bfloat16* __restrict__ Ahg, const __nv_bfloat16* __restrict__ Alg,
    const __nv_bfloat16* __restrict__ Bhg, const __nv_bfloat16* __restrict__ Blg,
    const float* __restrict__ bias, const float* __restrict__ resid,
    float* __restrict__ C, __nv_bfloat16* __restrict__ Ch, __nv_bfloat16* __restrict__ Cl,
    int M, int N, int K)
{
    extern __shared__ __align__(128) char smem[];
    const uint32_t sb0 = smem_u32(smem);

    const int tid  = threadIdx.x;
    const int w    = tid >> 5, lane = tid & 31;
    const int m0   = blockIdx.y * 128, n0 = blockIdx.x * 128;
    const int wm   = (w & 3) * 32;
    const int wn   = (w >> 2) * 32;

    const __nv_bfloat16* srcs[4] = {
        Ahg + (size_t)m0 * K, Alg + (size_t)m0 * K,
        Bhg + (size_t)n0 * K, Blg + (size_t)n0 * K };

    // cp.async loader: 4 x 16B per thread per stage (2048 chunks)
    auto load_stage = [&](int s) {
        uint32_t base = sb0 + (uint32_t)((s % NST) * STAGE_B);
        #pragma unroll
        for (int u = 0; u < 4; u++) {
            int f = tid + u * 512;
            int arr = f >> 9;
            int rem = f & 511;
            int row = rem >> 2, ch = rem & 3;
            cpa16(base + (uint32_t)(arr * ARR_B + row * 80 + ch * 16),
                  srcs[arr] + (size_t)row * K + s * 32 + ch * 8);
        }
    };

    // ldmatrix per-lane offsets (bytes)
    const uint32_t a_lane = (uint32_t)((wm + (lane & 15)) * 80 + (lane >> 4) * 16);
    const uint32_t b_lane = (uint32_t)(
        (wn + ((lane >> 4) & 1) * 8 + (lane & 7)) * 80 + ((lane >> 3) & 1) * 16);

    float acc[2][4][4] = {};
    const int NK = K >> 5;

    load_stage(0); cpa_commit();
    load_stage(1); cpa_commit();

    for (int kt = 0; kt < NK; kt++) {
        cpa_wait1();
        __syncthreads();
        if (kt + 2 < NK) load_stage(kt + 2);
        cpa_commit();

        const uint32_t sk = sb0 + (uint32_t)((kt % NST) * STAGE_B);
        const uint32_t aAh = sk, aAl = sk + ARR_B, aBh = sk + 2 * ARR_B, aBl = sk + 3 * ARR_B;

        #pragma unroll
        for (int kk = 0; kk < 2; kk++) {
            const uint32_t kof = (uint32_t)(kk * 32);
            uint32_t ah[2][4], al[2][4];
            #pragma unroll
            for (int mi = 0; mi < 2; mi++) {
                uint32_t off = a_lane + (uint32_t)(mi * 16 * 80) + kof;
                ldsm4(ah[mi], aAh + off);
                ldsm4(al[mi], aAl + off);
            }
            uint32_t bh[2][4], bl[2][4];
            #pragma unroll
            for (int j = 0; j < 2; j++) {
                uint32_t off = b_lane + (uint32_t)(j * 16 * 80) + kof;
                ldsm4(bh[j], aBh + off);
                ldsm4(bl[j], aBl + off);
            }
            #pragma unroll
            for (int mi = 0; mi < 2; mi++) {
                #pragma unroll
                for (int ni = 0; ni < 4; ni++) {
                    int j = ni >> 1, s = (ni & 1) * 2;
                    mma16816(acc[mi][ni], ah[mi], bh[j][s], bh[j][s + 1]);
                    mma16816(acc[mi][ni], ah[mi], bl[j][s], bl[j][s + 1]);
                    mma16816(acc[mi][ni], al[mi], bh[j][s], bh[j][s + 1]);
                }
            }
        }
    }

    // epilogue
    const int rbase = m0 + wm + (lane >> 2);
    const int cgrp  = (lane & 3) * 2;
    #pragma unroll
    for (int mi = 0; mi < 2; mi++) {
        int r1 = rbase + mi * 16;
        int r2 = r1 + 8;
        #pragma unroll
        for (int ni = 0; ni < 4; ni++) {
            int col = n0 + wn + ni * 8 + cgrp;
            float2 bv = *reinterpret_cast<const float2*>(bias + col);
            float2 v1 = make_float2(acc[mi][ni][0] + bv.x, acc[mi][ni][1] + bv.y);
            float2 v2 = make_float2(acc[mi][ni][2] + bv.x, acc[mi][ni][3] + bv.y);
            if (MODE == 0) {
                float2 q1 = *reinterpret_cast<const float2*>(resid + (size_t)r1 * N + col);
                float2 q2 = *reinterpret_cast<const float2*>(resid + (size_t)r2 * N + col);
                v1.x += q1.x; v1.y += q1.y; v2.x += q2.x; v2.y += q2.y;
                *reinterpret_cast<float2*>(C + (size_t)r1 * N + col) = v1;
                *reinterpret_cast<float2*>(C + (size_t)r2 * N + col) = v2;
            } else {
                v1.x = fmaxf(v1.x, 0.f); v1.y = fmaxf(v1.y, 0.f);
                v2.x = fmaxf(v2.x, 0.f); v2.y = fmaxf(v2.y, 0.f);
                __nv_bfloat16 lx, ly;
                uint32_t h1 = pack_split(v1.x, v1.y, lx, ly);
                __nv_bfloat162 lo1(lx, ly);
                *reinterpret_cast<uint32_t*>(Ch + (size_t)r1 * N + col) = h1;
                *reinterpret_cast<uint32_t*>(Cl + (size_t)r1 * N + col) =
                    *reinterpret_cast<uint32_t*>(&lo1);
                uint32_t h2 = pack_split(v2.x, v2.y, lx, ly);
                __nv_bfloat162 lo2(lx, ly);
                *reinterpret_cast<uint32_t*>(Ch + (size_t)r2 * N + col) = h2;
                *reinterpret_cast<uint32_t*>(Cl + (size_t)r2 * N + col) =
                    *reinterpret_cast<uint32_t*>(&lo2);
            }
        }
    }
}

// ---------------- embedding + positional encoding ----------------
__global__ void k_embed(const int* __restrict__ x, const float* __restrict__ emb,
                        const float* __restrict__ pe, float* __restrict__ h)
{
    int i = blockIdx.x * blockDim.x + threadIdx.x;
    const int n4 = cBS * cD / 4;
    if (i >= n4) return;
    int d4 = i & (cD / 4 - 1);
    int bs = i >> 7;
    int s  = bs % cS;
    int tok = x[bs];
    float4 e = reinterpret_cast<const float4*>(emb)[tok * (cD / 4) + d4];
    float4 p = reinterpret_cast<const float4*>(pe)[s * (cD / 4) + d4];
    const float sc = 22.62741699796952f;    // sqrt(512)
    float4 r;
    r.x = e.x * sc + p.x; r.y = e.y * sc + p.y;
    r.z = e.z * sc + p.z; r.w = e.w * sc + p.w;
    reinterpret_cast<float4*>(h)[i] = r;
}

// ---------------- fused QKV: [BSH,64] @ W^T for W in {Wq,Wk,Wv} --------------
// q is pre-scaled by 0.125 and written split bf16; k written split bf16; v fp32.
__global__ __launch_bounds__(256) void k_qkv(
    const float* __restrict__ h,
    const float* __restrict__ Wq, const float* __restrict__ Wk, const float* __restrict__ Wv,
    __nv_bfloat16* __restrict__ qh, __nv_bfloat16* __restrict__ ql,
    __nv_bfloat16* __restrict__ kh, __nv_bfloat16* __restrict__ kl,
    float* __restrict__ v)
{
    __shared__ __align__(16) float xs[64][68];
    __shared__ __align__(16) float ws[64][64];
    int tid = threadIdx.x;
    int tx = tid & 15, ty = tid >> 4;
    int row0 = blockIdx.x * 64;

    #pragma unroll
    for (int u = 0; u < 4; u++) {
        int f = tid + u * 256;
        int r = f >> 4, c4 = f & 15;
        float4 val = reinterpret_cast<const float4*>(h + (size_t)(row0 + r) * 64)[c4];
        *reinterpret_cast<float4*>(&xs[r][c4 * 4]) = val;
    }

    const float* Wm[3] = {Wq, Wk, Wv};
    #pragma unroll
    for (int m = 0; m < 3; m++) {
        __syncthreads();
        #pragma unroll
        for (int u = 0; u < 4; u++) {
            int f = tid + u * 256;
            int e = f >> 4, c4 = f & 15;
            float4 w4 = reinterpret_cast<const float4*>(Wm[m] + e * 64)[c4];
            ws[c4 * 4 + 0][e] = w4.x;
            ws[c4 * 4 + 1][e] = w4.y;
            ws[c4 * 4 + 2][e] = w4.z;
            ws[c4 * 4 + 3][e] = w4.w;
        }
        __syncthreads();
        float acc[4][4] = {};
        #pragma unroll
        for (int d = 0; d < 64; d++) {
            float a0 = xs[ty * 4 + 0][d];
            float a1 = xs[ty * 4 + 1][d];
            float a2 = xs[ty * 4 + 2][d];
            float a3 = xs[ty * 4 + 3][d];
            float4 b4 = *reinterpret_cast<const float4*>(&ws[d][tx * 4]);
            acc[0][0] += a0 * b4.x; acc[0][1] += a0 * b4.y; acc[0][2] += a0 * b4.z; acc[0][3] += a0 * b4.w;
            acc[1][0] += a1 * b4.x; acc[1][1] += a1 * b4.y; acc[1][2] += a1 * b4.z; acc[1][3] += a1 * b4.w;
            acc[2][0] += a2 * b4.x; acc[2][1] += a2 * b4.y; acc[2][2] += a2 * b4.z; acc[2][3] += a2 * b4.w;
            acc[3][0] += a3 * b4.x; acc[3][1] += a3 * b4.y; acc[3][2] += a3 * b4.z; acc[3][3] += a3 * b4.w;
        }
        #pragma unroll
        for (int i = 0; i < 4; i++) {
            size_t off = (size_t)(row0 + ty * 4 + i) * 64 + tx * 4;
            if (m == 2) {
                float4 r4 = make_float4(acc[i][0], acc[i][1], acc[i][2], acc[i][3]);
                *reinterpret_cast<float4*>(v + off) = r4;
            } else {
                float sc = (m == 0) ? 0.125f : 1.0f;
                float x0 = acc[i][0] * sc, x1 = acc[i][1] * sc;
                float x2 = acc[i][2] * sc, x3 = acc[i][3] * sc;
                __nv_bfloat16 l0, l1, l2, l3;
                uint32_t h01 = pack_split(x0, x1, l0, l1);
                uint32_t h23 = pack_split(x2, x3, l2, l3);
                __nv_bfloat162 lo01(l0, l1), lo23(l2, l3);
                __nv_bfloat16* ph = (m == 0) ? qh : kh;
                __nv_bfloat16* pl = (m == 0) ? ql : kl;
                *reinterpret_cast<uint2*>(ph + off) = make_uint2(h01, h23);
                *reinterpret_cast<uint2*>(pl + off) =
                    make_uint2(*reinterpret_cast<uint32_t*>(&lo01),
                               *reinterpret_cast<uint32_t*>(&lo23));
            }
        }
    }
}

// ---------------- tensor-core flash attention (bf16x3, 64x64 tiles) ----------
// 256 threads / 8 warps; warp grid 2(m) x 4(n), warp tile 32x16.
static constexpr int AST = 72;                         // bf16 row stride (144 B)
static constexpr int OQH = 0;
static constexpr int OQL = OQH + 64 * AST * 2;         //  9216
static constexpr int OKH = OQL + 64 * AST * 2;         // 18432
static constexpr int OKL = OKH + 64 * AST * 2;         // 27648
static constexpr int OVH = OKL + 64 * AST * 2;         // 36864
static constexpr int OVL = OVH + 64 * AST * 2;         // 46080
static constexpr int OPH = OVL + 64 * AST * 2;         // 55296
static constexpr int OPL = OPH + 64 * AST * 2;         // 64512
static constexpr int OPS = OPL + 64 * AST * 2;         // 73728
static constexpr int OMS = OPS + 64 * 68 * 4;          // 91136
static constexpr int OLS = OMS + 64 * 4;
static constexpr int OAS = OLS + 64 * 4;
static constexpr int ATTN_SMEM_BYTES = OAS + 64 * 4;   // 91904

__global__ __launch_bounds__(256) void k_attn(
    const __nv_bfloat16* __restrict__ qhg, const __nv_bfloat16* __restrict__ qlg,
    const __nv_bfloat16* __restrict__ khg, const __nv_bfloat16* __restrict__ klg,
    const float* __restrict__ vg,
    __nv_bfloat16* __restrict__ oh, __nv_bfloat16* __restrict__ ol)
{
    extern __shared__ __align__(128) char sm_[];
    const uint32_t ub = smem_u32(sm_);
    __nv_bfloat16* Qh = (__nv_bfloat16*)(sm_ + OQH);
    __nv_bfloat16* Ql = (__nv_bfloat16*)(sm_ + OQL);
    __nv_bfloat16* Kh = (__nv_bfloat16*)(sm_ + OKH);
    __nv_bfloat16* Kl = (__nv_bfloat16*)(sm_ + OKL);
    __nv_bfloat16* Vh = (__nv_bfloat16*)(sm_ + OVH);
    __nv_bfloat16* Vl = (__nv_bfloat16*)(sm_ + OVL);
    __nv_bfloat16* Ph = (__nv_bfloat16*)(sm_ + OPH);
    __nv_bfloat16* Pl = (__nv_bfloat16*)(sm_ + OPL);
    float* ps  = (float*)(sm_ + OPS);
    float* m_s = (float*)(sm_ + OMS);
    float* l_s = (float*)(sm_ + OLS);
    float* a_s = (float*)(sm_ + OAS);

    const int tid = threadIdx.x;
    const int w = tid >> 5, lane = tid & 31;
    const int wm = (w & 1) * 32;          // q rows
    const int wn = (w >> 1) * 16;         // 16-wide n slice
    const int s0 = blockIdx.x * 64;
    const int bh = blockIdx.y;
    const int b = bh >> 3, hh = bh & 7;
    const size_t base = (size_t)b * cS * cD + hh * 64;

    // ldmatrix lane offsets (bytes, stride 144)
    const uint32_t a_lane = (uint32_t)((wm + (lane & 15)) * 144 + (lane >> 4) * 16);
    const uint32_t b_lane = (uint32_t)(
        (wn + ((lane >> 4) & 1) * 8 + (lane & 7)) * 144 + ((lane >> 3) & 1) * 16);

    // load Q tile (split bf16, direct copy); zero tail rows
    #pragma unroll
    for (int u = 0; u < 2; u++) {
        int f = tid + u * 256;
        int r = f >> 3, ch = f & 7;
        uint4 zero = make_uint4(0, 0, 0, 0);
        uint4 hv = zero, lv = zero;
        if (s0 + r < cS) {
            hv = *reinterpret_cast<const uint4*>(qhg + base + (size_t)(s0 + r) * cD + ch * 8);
            lv = *reinterpret_cast<const uint4*>(qlg + base + (size_t)(s0 + r) * cD + ch * 8);
        }
        *reinterpret_cast<uint4*>(Qh + r * AST + ch * 8) = hv;
        *reinterpret_cast<uint4*>(Ql + r * AST + ch * 8) = lv;
    }
    if (tid < 64) { m_s[tid] = -1e30f; l_s[tid] = 0.f; }

    float oacc[2][2][4] = {};

    for (int kb = 0; kb < cS; kb += 64) {
        __syncthreads();
        // K tile: split bf16 direct copy
        #pragma unroll
        for (int u = 0; u < 2; u++) {
            int f = tid + u * 256;
            int r = f >> 3, ch = f & 7;
            uint4 zero = make_uint4(0, 0, 0, 0);
            uint4 hv = zero, lv = zero;
            if (kb + r < cS) {
                hv = *reinterpret_cast<const uint4*>(khg + base + (size_t)(kb + r) * cD + ch * 8);
                lv = *reinterpret_cast<const uint4*>(klg + base + (size_t)(kb + r) * cD + ch * 8);
            }
            *reinterpret_cast<uint4*>(Kh + r * AST + ch * 8) = hv;
            *reinterpret_cast<uint4*>(Kl + r * AST + ch * 8) = lv;
        }
        // V tile: fp32 load, split + transpose store  Vh/Vl[e][key]
        #pragma unroll
        for (int u = 0; u < 4; u++) {
            int f = tid + u * 256;
            int r = f >> 4, c4 = f & 15;
            float4 vv = make_float4(0.f, 0.f, 0.f, 0.f);
            if (kb + r < cS)
                vv = *reinterpret_cast<const float4*>(vg + base + (size_t)(kb + r) * cD + c4 * 4);
            __nv_bfloat16 l0, l1, l2, l3;
            __nv_bfloat16 h0 = __float2bfloat16_rn(vv.x);
            __nv_bfloat16 h1 = __float2bfloat16_rn(vv.y);
            __nv_bfloat16 h2 = __float2bfloat16_rn(vv.z);
            __nv_bfloat16 h3 = __float2bfloat16_rn(vv.w);
            l0 = __float2bfloat16_rn(vv.x - __bfloat162float(h0));
            l1 = __float2bfloat16_rn(vv.y - __bfloat162float(h1));
            l2 = __float2bfloat16_rn(vv.z - __bfloat162float(h2));
            l3 = __float2bfloat16_rn(vv.w - __bfloat162float(h3));
            int e0 = c4 * 4;
            Vh[(e0 + 0) * AST + r] = h0; Vl[(e0 + 0) * AST + r] = l0;
            Vh[(e0 + 1) * AST + r] = h1; Vl[(e0 + 1) * AST + r] = l1;
            Vh[(e0 + 2) * AST + r] = h2; Vl[(e0 + 2) * AST + r] = l2;
            Vh[(e0 + 3) * AST + r] = h3; Vl[(e0 + 3) * AST + r] = l3;
        }
        __syncthreads();

        // ---- S = Q K^T (3-term bf16), accumulate fp32 frags ----
        float scv[2][2][4] = {};
        #pragma unroll
        for (int ks = 0; ks < 4; ks++) {
            const uint32_t kof = (uint32_t)(ks * 32);
            uint32_t qa[2][4], qb[2][4];
            #pragma unroll
            for (int mi = 0; mi < 2; mi++) {
                uint32_t off = a_lane + (uint32_t)(mi * 16 * 144) + kof;
                ldsm4(qa[mi], ub + OQH + off);
                ldsm4(qb[mi], ub + OQL + off);
            }
            uint32_t kh4[4], kl4[4];
            ldsm4(kh4, ub + OKH + b_lane + kof);
            ldsm4(kl4, ub + OKL + b_lane + kof);
            #pragma unroll
            for (int mi = 0; mi < 2; mi++) {
                #pragma unroll
                for (int nh = 0; nh < 2; nh++) {
                    int s = nh * 2;
                    mma16816(scv[mi][nh], qa[mi], kh4[s], kh4[s + 1]);
                    mma16816(scv[mi][nh], qa[mi], kl4[s], kl4[s + 1]);
                    mma16816(scv[mi][nh], qb[mi], kh4[s], kh4[s + 1]);
                }
            }
        }
        // store S to ps (fp32), mask tail cols
        #pragma unroll
        for (int mi = 0; mi < 2; mi++) {
            int r1 = wm + mi * 16 + (lane >> 2);
            int r2 = r1 + 8;
            #pragma unroll
            for (int nh = 0; nh < 2; nh++) {
                int col = wn + nh * 8 + (lane & 3) * 2;
                int g = kb + col;
                float2 v1, v2;
                v1.x = (g     < cS) ? scv[mi][nh][0] : -1e30f;
                v1.y = (g + 1 < cS) ? scv[mi][nh][1] : -1e30f;
                v2.x = (g     < cS) ? scv[mi][nh][2] : -1e30f;
                v2.y = (g + 1 < cS) ? scv[mi][nh][3] : -1e30f;
                *reinterpret_cast<float2*>(&ps[r1 * 68 + col]) = v1;
                *reinterpret_cast<float2*>(&ps[r2 * 68 + col]) = v2;
            }
        }
        __syncthreads();

        // ---- online softmax; write P split bf16 ----
        {
            int row = tid >> 2, qt = tid & 3;
            float* pr = &ps[row * 68 + qt * 16];
            float lm = -1e30f;
            #pragma unroll
            for (int c = 0; c < 16; c++) lm = fmaxf(lm, pr[c]);
            lm = fmaxf(lm, __shfl_xor_sync(0xffffffffu, lm, 1));
            lm = fmaxf(lm, __shfl_xor_sync(0xffffffffu, lm, 2));
            float m_old = m_s[row];
            float m_new = fmaxf(m_old, lm);
            float alpha = __expf(m_old - m_new);
            float lsum = 0.f;
            float pv[16];
            #pragma unroll
            for (int c = 0; c < 16; c++) {
                float p = __expf(pr[c] - m_new);
                pv[c] = p;
                lsum += p;
            }
            lsum += __shfl_xor_sync(0xffffffffu, lsum, 1);
            lsum += __shfl_xor_sync(0xffffffffu, lsum, 2);
            int cbase = row * AST + qt * 16;
            #pragma unroll
            for (int c = 0; c < 16; c += 2) {
                __nv_bfloat16 lx, ly;
                uint32_t hp = pack_split(pv[c], pv[c + 1], lx, ly);
                __nv_bfloat162 lp(lx, ly);
                *reinterpret_cast<uint32_t*>(Ph + cbase + c) = hp;
                *reinterpret_cast<uint32_t*>(Pl + cbase + c) =
                    *reinterpret_cast<uint32_t*>(&lp);
            }
            if (qt == 0) {
                m_s[row] = m_new;
                l_s[row] = l_s[row] * alpha + lsum;
                a_s[row] = alpha;
            }
        }
        __syncthreads();

        // rescale O by alpha
        #pragma unroll
        for (int mi = 0; mi < 2; mi++) {
            float al1 = a_s[wm + mi * 16 + (lane >> 2)];
            float al2 = a_s[wm + mi * 16 + (lane >> 2) + 8];
            #pragma unroll
            for (int nh = 0; nh < 2; nh++) {
                oacc[mi][nh][0] *= al1; oacc[mi][nh][1] *= al1;
                oacc[mi][nh][2] *= al2; oacc[mi][nh][3] *= al2;
            }
        }

        // ---- O += P V (3-term bf16) ----
        #pragma unroll
        for (int ks = 0; ks < 4; ks++) {
            const uint32_t kof = (uint32_t)(ks * 32);
            uint32_t pa[2][4], pb[2][4];
            #pragma unroll
            for (int mi = 0; mi < 2; mi++) {
                uint32_t off = a_lane + (uint32_t)(mi * 16 * 144) + kof;
                ldsm4(pa[mi], ub + OPH + off);
                ldsm4(pb[mi], ub + OPL + off);
            }
            uint32_t vh4[4], vl4[4];
            ldsm4(vh4, ub + OVH + b_lane + kof);
            ldsm4(vl4, ub + OVL + b_lane + kof);
            #pragma unroll
            for (int mi = 0; mi < 2; mi++) {
                #pragma unroll
                for (int nh = 0; nh < 2; nh++) {
                    int s = nh * 2;
                    mma16816(oacc[mi][nh], pa[mi], vh4[s], vh4[s + 1]);
                    mma16816(oacc[mi][nh], pa[mi], vl4[s], vl4[s + 1]);
                    mma16816(oacc[mi][nh], pb[mi], vh4[s], vh4[s + 1]);
                }
            }
        }
    }
    __syncthreads();

    // final: scale by 1/l, split-write o
    #pragma unroll
    for (int mi = 0; mi < 2; mi++) {
        int rr1 = wm + mi * 16 + (lane >> 2);
        int rr2 = rr1 + 8;
        float inv1 = 1.f / l_s[rr1];
        float inv2 = 1.f / l_s[rr2];
        #pragma unroll
        for (int nh = 0; nh < 2; nh++) {
            int col = wn + nh * 8 + (lane & 3) * 2;
            int s1 = s0 + rr1, s2 = s0 + rr2;
            if (s1 < cS) {
                __nv_bfloat16 lx, ly;
                uint32_t hp = pack_split(oacc[mi][nh][0] * inv1, oacc[mi][nh][1] * inv1, lx, ly);
                __nv_bfloat162 lp(lx, ly);
                size_t off = base + (size_t)s1 * cD + col;
                *reinterpret_cast<uint32_t*>(oh + off) = hp;
                *reinterpret_cast<uint32_t*>(ol + off) = *reinterpret_cast<uint32_t*>(&lp);
            }
            if (s2 < cS) {
                __nv_bfloat16 lx, ly;
                uint32_t hp = pack_split(oacc[mi][nh][2] * inv2, oacc[mi][nh][3] * inv2, lx, ly);
                __nv_bfloat162 lp(lx, ly);
                size_t off = base + (size_t)s2 * cD + col;
                *reinterpret_cast<uint32_t*>(oh + off) = hp;
                *reinterpret_cast<uint32_t*>(ol + off) = *reinterpret_cast<uint32_t*>(&lp);
            }
        }
    }
}

// ---------------- LayerNorm over rows of 512 (optional split output) --------
template<bool SPLIT>
__global__ void k_ln(const float* __restrict__ x, const float* __restrict__ w,
                     const float* __restrict__ bb, float* __restrict__ out,
                     __nv_bfloat16* __restrict__ oh, __nv_bfloat16* __restrict__ ol)
{
    __shared__ float red[4];
    int row = blockIdx.x;
    int t = threadIdx.x;
    const float4 v = reinterpret_cast<const float4*>(x + (size_t)row * cD)[t];
    float s = v.x + v.y + v.z + v.w;
    #pragma unroll
    for (int o = 16; o > 0; o >>= 1) s += __shfl_xor_sync(0xffffffffu, s, o);
    if ((t & 31) == 0) red[t >> 5] = s;
    __syncthreads();
    float mean = (red[0] + red[1] + red[2] + red[3]) * (1.0f / cD);
    float dx = v.x - mean, dy = v.y - mean, dz = v.z - mean, dw = v.w - mean;
    float s2 = dx * dx + dy * dy + dz * dz + dw * dw;
    #pragma unroll
    for (int o = 16; o > 0; o >>= 1) s2 += __shfl_xor_sync(0xffffffffu, s2, o);
    __syncthreads();
    if ((t & 31) == 0) red[t >> 5] = s2;
    __syncthreads();
    float var = (red[0] + red[1] + red[2] + red[3]) * (1.0f / cD);
    float inv = rsqrtf(var + 1e-5f);
    float4 wv = reinterpret_cast<const float4*>(w)[t];
    float4 bv = reinterpret_cast<const float4*>(bb)[t];
    float4 r4;
    r4.x = dx * inv * wv.x + bv.x;
    r4.y = dy * inv * wv.y + bv.y;
    r4.z = dz * inv * wv.z + bv.z;
    r4.w = dw * inv * wv.w + bv.w;
    reinterpret_cast<float4*>(out + (size_t)row * cD)[t] = r4;
    if (SPLIT) {
        size_t off = (size_t)row * cD + t * 4;
        __nv_bfloat16 lx, ly;
        uint32_t h01 = pack_split(r4.x, r4.y, lx, ly);
        __nv_bfloat162 lo01(lx, ly);
        uint32_t h23 = pack_split(r4.z, r4.w, lx, ly);
        __nv_bfloat162 lo23(lx, ly);
        *reinterpret_cast<uint2*>(oh + off) = make_uint2(h01, h23);
        *reinterpret_cast<uint2*>(ol + off) =
            make_uint2(*reinterpret_cast<uint32_t*>(&lo01),
                       *reinterpret_cast<uint32_t*>(&lo23));
    }
}

// ---------------- driver ----------------
extern "C" void kernel_launch(void* const* d_in, const int* in_sizes, int n_in,
                              void* d_out, int out_size)
{
    const int*   x    = (const int*)  d_in[0];
    const float* emb  = (const float*)d_in[1];
    const float* pe   = (const float*)d_in[2];
    const float* Wq   = (const float*)d_in[3];
    const float* Wk   = (const float*)d_in[4];
    const float* Wv   = (const float*)d_in[5];
    const float* Wo   = (const float*)d_in[6];
    const float* bo   = (const float*)d_in[7];
    const float* ln1w = (const float*)d_in[8];
    const float* ln1b = (const float*)d_in[9];
    const float* W1   = (const float*)d_in[10];
    const float* b1   = (const float*)d_in[11];
    const float* W2   = (const float*)d_in[12];
    const float* b2   = (const float*)d_in[13];
    const float* ln2w = (const float*)d_in[14];
    const float* ln2b = (const float*)d_in[15];
    float* out = (float*)d_out;

    float *h, *v, *t, *n1, *t2;
    __nv_bfloat16 *qh, *ql, *kh, *kl, *ah, *al, *fh, *fl, *wh, *wl;
    cudaGetSymbolAddress((void**)&h,  g_h);
    cudaGetSymbolAddress((void**)&v,  g_v);
    cudaGetSymbolAddress((void**)&t,  g_t);
    cudaGetSymbolAddress((void**)&n1, g_n1);
    cudaGetSymbolAddress((void**)&t2, g_t2);
    cudaGetSymbolAddress((void**)&qh, g_qh);
    cudaGetSymbolAddress((void**)&ql, g_ql);
    cudaGetSymbolAddress((void**)&kh, g_kh);
    cudaGetSymbolAddress((void**)&kl, g_kl);
    cudaGetSymbolAddress((void**)&ah, g_ah);
    cudaGetSymbolAddress((void**)&al, g_al);
    cudaGetSymbolAddress((void**)&fh, g_fh);
    cudaGetSymbolAddress((void**)&fl, g_fl);
    cudaGetSymbolAddress((void**)&wh, g_wh);
    cudaGetSymbolAddress((void**)&wl, g_wl);

    cudaFuncSetAttribute(k_attn, cudaFuncAttributeMaxDynamicSharedMemorySize, ATTN_SMEM_BYTES);
    cudaFuncSetAttribute(mma_gemm<0>, cudaFuncAttributeMaxDynamicSharedMemorySize, GEMM_SMEM);
    cudaFuncSetAttribute(mma_gemm<1>, cudaFuncAttributeMaxDynamicSharedMemorySize, GEMM_SMEM);

    k_embed<<<(cBS * cD / 4 + 255) / 256, 256>>>(x, emb, pe, h);

    for (int l = 0; l < cL; l++) {
        k_qkv<<<cBSH / 64, 256>>>(h, Wq + l * cHD * cHD, Wk + l * cHD * cHD,
                                  Wv + l * cHD * cHD, qh, ql, kh, kl, v);
        // attention -> o (split bf16 in ah/al)
        k_attn<<<dim3((cS + 63) / 64, cB * cH), 256, ATTN_SMEM_BYTES>>>(
            qh, ql, kh, kl, v, ah, al);

        // t = o @ Wo^T + bo + h
        k_split<<<(cD * cD / 4 + 255) / 256, 256>>>(Wo + (size_t)l * cD * cD, wh, wl, cD * cD / 4);
        mma_gemm<0><<<dim3(cD / 128, cBS / 128), 512, GEMM_SMEM>>>(
            ah, al, wh, wl, bo + l * cD, h, t, nullptr, nullptr, cBS, cD, cD);
        k_ln<true><<<cBS, 128>>>(t, ln1w + l * cD, ln1b + l * cD, n1, ah, al);

        // f1 = relu(n1 @ W1^T + b1)  (split bf16 out)
        k_split<<<(cF * cD / 4 + 255) / 256, 256>>>(W1 + (size_t)l * cF * cD, wh, wl, cF * cD / 4);
        mma_gemm<1><<<dim3(cF / 128, cBS / 128), 512, GEMM_SMEM>>>(
            ah, al, wh, wl, b1 + l * cF, nullptr, nullptr, fh, fl, cBS, cF, cD);

        // t2 = f1 @ W2^T + b2 + n1
        k_split<<<(cF * cD / 4 + 255) / 256, 256>>>(W2 + (size_t)l * cD * cF, wh, wl, cF * cD / 4);
        mma_gemm<0><<<dim3(cD / 128, cBS / 128), 512, GEMM_SMEM>>>(
            fh, fl, wh, wl, b2 + l * cD, n1, t2, nullptr, nullptr, cBS, cD, cF);

        k_ln<false><<<cBS, 128>>>(t2, ln2w + l * cD, ln2b + l * cD,
                                  (l == cL - 1) ? out : h, nullptr, nullptr);
    }
}

// round 16
// speedup vs baseline: 1.2960x; 1.1210x over previous
#include <cuda_runtime.h>
#include <cuda_bf16.h>
#include <stdint.h>
#include <math.h>

// ---------------- problem constants ----------------
static constexpr int cB   = 32;
static constexpr int cS   = 744;
static constexpr int cD   = 512;
static constexpr int cH   = 8;
static constexpr int cHD  = 64;
static constexpr int cL   = 4;
static constexpr int cF   = 2048;           // EXP * D
static constexpr int cBS  = cB * cS;        // 23808 = 186 * 128
static constexpr int cBSH = cBS * cH;       // 190464

// ---------------- scratch (device globals; no allocations allowed) ----------
__device__ float g_h [cBS * cD];
__device__ float g_v [cBS * cD];
__device__ float g_t [cBS * cD];
__device__ float g_n1[cBS * cD];
__device__ float g_t2[cBS * cD];
// bf16 hi/lo split buffers
__device__ __nv_bfloat16 g_qh[(size_t)cBS * cD];
__device__ __nv_bfloat16 g_ql[(size_t)cBS * cD];
__device__ __nv_bfloat16 g_kh[(size_t)cBS * cD];
__device__ __nv_bfloat16 g_kl[(size_t)cBS * cD];
__device__ __nv_bfloat16 g_ah[(size_t)cBS * cD];   // activation split (o, then n1)
__device__ __nv_bfloat16 g_al[(size_t)cBS * cD];
__device__ __nv_bfloat16 g_fh[(size_t)cBS * cF];   // f1 split
__device__ __nv_bfloat16 g_fl[(size_t)cBS * cF];
__device__ __nv_bfloat16 g_wh[(size_t)cD * cF];    // weight split (reused per GEMM)
__device__ __nv_bfloat16 g_wl[(size_t)cD * cF];

// =====================================================================
// helpers
// =====================================================================
__device__ __forceinline__ uint32_t smem_u32(const void* p) {
    uint32_t a;
    asm("{ .reg .u64 t; cvta.to.shared.u64 t, %1; cvt.u32.u64 %0, t; }" : "=r"(a) : "l"(p));
    return a;
}
__device__ __forceinline__ void ldsm4(uint32_t* r, uint32_t a) {
    asm volatile("ldmatrix.sync.aligned.m8n8.x4.shared.b16 {%0,%1,%2,%3}, [%4];"
                 : "=r"(r[0]), "=r"(r[1]), "=r"(r[2]), "=r"(r[3]) : "r"(a));
}
__device__ __forceinline__ void mma16816(float* c, const uint32_t* a,
                                         uint32_t b0, uint32_t b1) {
    asm volatile(
        "mma.sync.aligned.m16n8k16.row.col.f32.bf16.bf16.f32 "
        "{%0,%1,%2,%3}, {%4,%5,%6,%7}, {%8,%9}, {%0,%1,%2,%3};"
        : "+f"(c[0]), "+f"(c[1]), "+f"(c[2]), "+f"(c[3])
        : "r"(a[0]), "r"(a[1]), "r"(a[2]), "r"(a[3]), "r"(b0), "r"(b1));
}
__device__ __forceinline__ void cpa16(uint32_t dst, const void* src) {
    asm volatile("cp.async.cg.shared.global [%0], [%1], 16;" :: "r"(dst), "l"(src));
}
__device__ __forceinline__ void cpa_commit() {
    asm volatile("cp.async.commit_group;" ::: "memory");
}
__device__ __forceinline__ void cpa_wait1() {
    asm volatile("cp.async.wait_group 1;" ::: "memory");
}
__device__ __forceinline__ uint32_t pack_split(float x, float y,
                                               __nv_bfloat16& lx, __nv_bfloat16& ly) {
    __nv_bfloat16 hx = __float2bfloat16_rn(x);
    __nv_bfloat16 hy = __float2bfloat16_rn(y);
    lx = __float2bfloat16_rn(x - __bfloat162float(hx));
    ly = __float2bfloat16_rn(y - __bfloat162float(hy));
    __nv_bfloat162 t(hx, hy);
    return *reinterpret_cast<uint32_t*>(&t);
}

// ---------------- fp32 -> bf16 hi/lo split (weights) ----------------
__global__ void k_split(const float* __restrict__ s, __nv_bfloat16* __restrict__ hi,
                        __nv_bfloat16* __restrict__ lo, int n4)
{
    int i = blockIdx.x * blockDim.x + threadIdx.x;
    if (i >= n4) return;
    float4 v = reinterpret_cast<const float4*>(s)[i];
    __nv_bfloat16 l0, l1, l2, l3;
    uint32_t h01 = pack_split(v.x, v.y, l0, l1);
    uint32_t h23 = pack_split(v.z, v.w, l2, l3);
    __nv_bfloat162 lo01(l0, l1), lo23(l2, l3);
    reinterpret_cast<uint2*>(hi)[i] = make_uint2(h01, h23);
    reinterpret_cast<uint2*>(lo)[i] = make_uint2(*reinterpret_cast<uint32_t*>(&lo01),
                                                *reinterpret_cast<uint32_t*>(&lo23));
}

// =====================================================================
// bf16x3 pipelined tensor GEMM (cp.async, 3 stages, swizzled 64B rows)
// C = A[M,K] @ B[N,K]^T + bias, A/B pre-split bf16 hi/lo.
// MODE 0: fp32 out + residual.  MODE 1: relu, split bf16 out (Ch/Cl).
// Tile 128(M)x64(N), K-block 32, 256 threads, warp grid 4(m)x2(n),
// warp tile 32x32.  2 CTAs/SM (73728 B smem, <=128 regs).
// Swizzle: byte offset = row*64 + ((g ^ ((row>>1)&3))<<4), g = granule.
// =====================================================================
static constexpr int OFF_AL  = 8192;
static constexpr int OFF_BH  = 16384;
static constexpr int OFF_BL  = 20480;
static constexpr int STAGE_B = 24576;
static constexpr int NST     = 3;
static constexpr int GEMM_SMEM = NST * STAGE_B;       // 73728 B

template<int MODE>
__global__ __launch_bounds__(256, 2) void mma_gemm(
    const __nv_bfloat16* __restrict__ Ahg, const __nv_bfloat16* __restrict__ Alg,
    const __nv_bfloat16* __restrict__ Bhg, const __nv_bfloat16* __restrict__ Blg,
    const float* __restrict__ bias, const float* __restrict__ resid,
    float* __restrict__ C, __nv_bfloat16* __restrict__ Ch, __nv_bfloat16* __restrict__ Cl,
    int M, int N, int K)
{
    extern __shared__ __align__(128) char smem[];
    const uint32_t sb0 = smem_u32(smem);

    const int tid  = threadIdx.x;
    const int w    = tid >> 5, lane = tid & 31;
    const int m0   = blockIdx.y * 128, n0 = blockIdx.x * 64;
    const int wm   = (w & 3) * 32;
    const int wn   = (w >> 2) * 32;

    // cp.async loader: 6 x 16B per thread per stage (1536 chunks)
    auto load_stage = [&](int s) {
        uint32_t base = sb0 + (uint32_t)((s % NST) * STAGE_B);
        #pragma unroll
        for (int u = 0; u < 4; u++) {                  // A hi (u<2) / A lo
            int f = tid + (u & 1) * 256;               // 0..511
            int row = f >> 2, g = f & 3;
            uint32_t dst = base + (uint32_t)((u < 2 ? 0 : OFF_AL)
                         + row * 64 + (((g ^ ((row >> 1) & 3))) << 4));
            const __nv_bfloat16* sp = (u < 2 ? Ahg : Alg)
                         + (size_t)(m0 + row) * K + s * 32 + g * 8;
            cpa16(dst, sp);
        }
        #pragma unroll
        for (int u = 0; u < 2; u++) {                  // B hi / B lo
            int row = tid >> 2, g = tid & 3;
            uint32_t dst = base + (uint32_t)((u == 0 ? OFF_BH : OFF_BL)
                         + row * 64 + (((g ^ ((row >> 1) & 3))) << 4));
            const __nv_bfloat16* sp = (u == 0 ? Bhg : Blg)
                         + (size_t)(n0 + row) * K + s * 32 + g * 8;
            cpa16(dst, sp);
        }
    };

    // ldmatrix per-lane addressing (swizzled)
    const int rowA  = wm + (lane & 15);
    const int maskA = (rowA >> 1) & 3;
    const int gA0   = lane >> 4;
    const uint32_t aBaseA = (uint32_t)(rowA * 64);
    const int rowB  = wn + ((lane >> 4) & 1) * 8 + (lane & 7);
    const int maskB = (rowB >> 1) & 3;
    const int gB0   = (lane >> 3) & 1;
    const uint32_t aBaseB = (uint32_t)(rowB * 64);

    float acc[2][4][4] = {};
    const int NK = K >> 5;

    load_stage(0); cpa_commit();
    load_stage(1); cpa_commit();

    for (int kt = 0; kt < NK; kt++) {
        cpa_wait1();
        __syncthreads();
        if (kt + 2 < NK) load_stage(kt + 2);
        cpa_commit();

        const uint32_t sk = sb0 + (uint32_t)((kt % NST) * STAGE_B);

        #pragma unroll
        for (int kk = 0; kk < 2; kk++) {
            const uint32_t swA = (uint32_t)(((gA0 + kk * 2) ^ maskA) << 4);
            const uint32_t swB = (uint32_t)(((gB0 + kk * 2) ^ maskB) << 4);
            uint32_t ah[2][4], al[2][4];
            #pragma unroll
            for (int mi = 0; mi < 2; mi++) {
                uint32_t off = aBaseA + (uint32_t)(mi * 1024) + swA;
                ldsm4(ah[mi], sk + off);
                ldsm4(al[mi], sk + OFF_AL + off);
            }
            uint32_t bh[2][4], bl[2][4];
            #pragma unroll
            for (int j = 0; j < 2; j++) {
                uint32_t off = aBaseB + (uint32_t)(j * 1024) + swB;
                ldsm4(bh[j], sk + OFF_BH + off);
                ldsm4(bl[j], sk + OFF_BL + off);
            }
            #pragma unroll
            for (int mi = 0; mi < 2; mi++) {
                #pragma unroll
                for (int ni = 0; ni < 4; ni++) {
                    int j = ni >> 1, s = (ni & 1) * 2;
                    mma16816(acc[mi][ni], ah[mi], bh[j][s], bh[j][s + 1]);
                    mma16816(acc[mi][ni], ah[mi], bl[j][s], bl[j][s + 1]);
                    mma16816(acc[mi][ni], al[mi], bh[j][s], bh[j][s + 1]);
                }
            }
        }
    }

    // epilogue
    const int rbase = m0 + wm + (lane >> 2);
    const int cgrp  = (lane & 3) * 2;
    #pragma unroll
    for (int mi = 0; mi < 2; mi++) {
        int r1 = rbase + mi * 16;
        int r2 = r1 + 8;
        #pragma unroll
        for (int ni = 0; ni < 4; ni++) {
            int col = n0 + wn + ni * 8 + cgrp;
            float2 bv = *reinterpret_cast<const float2*>(bias + col);
            float2 v1 = make_float2(acc[mi][ni][0] + bv.x, acc[mi][ni][1] + bv.y);
            float2 v2 = make_float2(acc[mi][ni][2] + bv.x, acc[mi][ni][3] + bv.y);
            if (MODE == 0) {
                float2 q1 = *reinterpret_cast<const float2*>(resid + (size_t)r1 * N + col);
                float2 q2 = *reinterpret_cast<const float2*>(resid + (size_t)r2 * N + col);
                v1.x += q1.x; v1.y += q1.y; v2.x += q2.x; v2.y += q2.y;
                *reinterpret_cast<float2*>(C + (size_t)r1 * N + col) = v1;
                *reinterpret_cast<float2*>(C + (size_t)r2 * N + col) = v2;
            } else {
                v1.x = fmaxf(v1.x, 0.f); v1.y = fmaxf(v1.y, 0.f);
                v2.x = fmaxf(v2.x, 0.f); v2.y = fmaxf(v2.y, 0.f);
                __nv_bfloat16 lx, ly;
                uint32_t h1 = pack_split(v1.x, v1.y, lx, ly);
                __nv_bfloat162 lo1(lx, ly);
                *reinterpret_cast<uint32_t*>(Ch + (size_t)r1 * N + col) = h1;
                *reinterpret_cast<uint32_t*>(Cl + (size_t)r1 * N + col) =
                    *reinterpret_cast<uint32_t*>(&lo1);
                uint32_t h2 = pack_split(v2.x, v2.y, lx, ly);
                __nv_bfloat162 lo2(lx, ly);
                *reinterpret_cast<uint32_t*>(Ch + (size_t)r2 * N + col) = h2;
                *reinterpret_cast<uint32_t*>(Cl + (size_t)r2 * N + col) =
                    *reinterpret_cast<uint32_t*>(&lo2);
            }
        }
    }
}

// ---------------- embedding + positional encoding ----------------
__global__ void k_embed(const int* __restrict__ x, const float* __restrict__ emb,
                        const float* __restrict__ pe, float* __restrict__ h)
{
    int i = blockIdx.x * blockDim.x + threadIdx.x;
    const int n4 = cBS * cD / 4;
    if (i >= n4) return;
    int d4 = i & (cD / 4 - 1);
    int bs = i >> 7;
    int s  = bs % cS;
    int tok = x[bs];
    float4 e = reinterpret_cast<const float4*>(emb)[tok * (cD / 4) + d4];
    float4 p = reinterpret_cast<const float4*>(pe)[s * (cD / 4) + d4];
    const float sc = 22.62741699796952f;    // sqrt(512)
    float4 r;
    r.x = e.x * sc + p.x; r.y = e.y * sc + p.y;
    r.z = e.z * sc + p.z; r.w = e.w * sc + p.w;
    reinterpret_cast<float4*>(h)[i] = r;
}

// ---------------- fused QKV: [BSH,64] @ W^T for W in {Wq,Wk,Wv} --------------
// q is pre-scaled by 0.125 and written split bf16; k written split bf16; v fp32.
__global__ __launch_bounds__(256) void k_qkv(
    const float* __restrict__ h,
    const float* __restrict__ Wq, const float* __restrict__ Wk, const float* __restrict__ Wv,
    __nv_bfloat16* __restrict__ qh, __nv_bfloat16* __restrict__ ql,
    __nv_bfloat16* __restrict__ kh, __nv_bfloat16* __restrict__ kl,
    float* __restrict__ v)
{
    __shared__ __align__(16) float xs[64][68];
    __shared__ __align__(16) float ws[64][64];
    int tid = threadIdx.x;
    int tx = tid & 15, ty = tid >> 4;
    int row0 = blockIdx.x * 64;

    #pragma unroll
    for (int u = 0; u < 4; u++) {
        int f = tid + u * 256;
        int r = f >> 4, c4 = f & 15;
        float4 val = reinterpret_cast<const float4*>(h + (size_t)(row0 + r) * 64)[c4];
        *reinterpret_cast<float4*>(&xs[r][c4 * 4]) = val;
    }

    const float* Wm[3] = {Wq, Wk, Wv};
    #pragma unroll
    for (int m = 0; m < 3; m++) {
        __syncthreads();
        #pragma unroll
        for (int u = 0; u < 4; u++) {
            int f = tid + u * 256;
            int e = f >> 4, c4 = f & 15;
            float4 w4 = reinterpret_cast<const float4*>(Wm[m] + e * 64)[c4];
            ws[c4 * 4 + 0][e] = w4.x;
            ws[c4 * 4 + 1][e] = w4.y;
            ws[c4 * 4 + 2][e] = w4.z;
            ws[c4 * 4 + 3][e] = w4.w;
        }
        __syncthreads();
        float acc[4][4] = {};
        #pragma unroll
        for (int d = 0; d < 64; d++) {
            float a0 = xs[ty * 4 + 0][d];
            float a1 = xs[ty * 4 + 1][d];
            float a2 = xs[ty * 4 + 2][d];
            float a3 = xs[ty * 4 + 3][d];
            float4 b4 = *reinterpret_cast<const float4*>(&ws[d][tx * 4]);
            acc[0][0] += a0 * b4.x; acc[0][1] += a0 * b4.y; acc[0][2] += a0 * b4.z; acc[0][3] += a0 * b4.w;
            acc[1][0] += a1 * b4.x; acc[1][1] += a1 * b4.y; acc[1][2] += a1 * b4.z; acc[1][3] += a1 * b4.w;
            acc[2][0] += a2 * b4.x; acc[2][1] += a2 * b4.y; acc[2][2] += a2 * b4.z; acc[2][3] += a2 * b4.w;
            acc[3][0] += a3 * b4.x; acc[3][1] += a3 * b4.y; acc[3][2] += a3 * b4.z; acc[3][3] += a3 * b4.w;
        }
        #pragma unroll
        for (int i = 0; i < 4; i++) {
            size_t off = (size_t)(row0 + ty * 4 + i) * 64 + tx * 4;
            if (m == 2) {
                float4 r4 = make_float4(acc[i][0], acc[i][1], acc[i][2], acc[i][3]);
                *reinterpret_cast<float4*>(v + off) = r4;
            } else {
                float sc = (m == 0) ? 0.125f : 1.0f;
                float x0 = acc[i][0] * sc, x1 = acc[i][1] * sc;
                float x2 = acc[i][2] * sc, x3 = acc[i][3] * sc;
                __nv_bfloat16 l0, l1, l2, l3;
                uint32_t h01 = pack_split(x0, x1, l0, l1);
                uint32_t h23 = pack_split(x2, x3, l2, l3);
                __nv_bfloat162 lo01(l0, l1), lo23(l2, l3);
                __nv_bfloat16* ph = (m == 0) ? qh : kh;
                __nv_bfloat16* pl = (m == 0) ? ql : kl;
                *reinterpret_cast<uint2*>(ph + off) = make_uint2(h01, h23);
                *reinterpret_cast<uint2*>(pl + off) =
                    make_uint2(*reinterpret_cast<uint32_t*>(&lo01),
                               *reinterpret_cast<uint32_t*>(&lo23));
            }
        }
    }
}

// ---------------- tensor-core flash attention (bf16x3, 64x64 tiles) ----------
// 256 threads / 8 warps; warp grid 2(m) x 4(n), warp tile 32x16.
static constexpr int AST = 72;                         // bf16 row stride (144 B)
static constexpr int OQH = 0;
static constexpr int OQL = OQH + 64 * AST * 2;         //  9216
static constexpr int OKH = OQL + 64 * AST * 2;         // 18432
static constexpr int OKL = OKH + 64 * AST * 2;         // 27648
static constexpr int OVH = OKL + 64 * AST * 2;         // 36864
static constexpr int OVL = OVH + 64 * AST * 2;         // 46080
static constexpr int OPH = OVL + 64 * AST * 2;         // 55296
static constexpr int OPL = OPH + 64 * AST * 2;         // 64512
static constexpr int OPS = OPL + 64 * AST * 2;         // 73728
static constexpr int OMS = OPS + 64 * 68 * 4;          // 91136
static constexpr int OLS = OMS + 64 * 4;
static constexpr int OAS = OLS + 64 * 4;
static constexpr int ATTN_SMEM_BYTES = OAS + 64 * 4;   // 91904

__global__ __launch_bounds__(256) void k_attn(
    const __nv_bfloat16* __restrict__ qhg, const __nv_bfloat16* __restrict__ qlg,
    const __nv_bfloat16* __restrict__ khg, const __nv_bfloat16* __restrict__ klg,
    const float* __restrict__ vg,
    __nv_bfloat16* __restrict__ oh, __nv_bfloat16* __restrict__ ol)
{
    extern __shared__ __align__(128) char sm_[];
    const uint32_t ub = smem_u32(sm_);
    __nv_bfloat16* Qh = (__nv_bfloat16*)(sm_ + OQH);
    __nv_bfloat16* Ql = (__nv_bfloat16*)(sm_ + OQL);
    __nv_bfloat16* Kh = (__nv_bfloat16*)(sm_ + OKH);
    __nv_bfloat16* Kl = (__nv_bfloat16*)(sm_ + OKL);
    __nv_bfloat16* Vh = (__nv_bfloat16*)(sm_ + OVH);
    __nv_bfloat16* Vl = (__nv_bfloat16*)(sm_ + OVL);
    __nv_bfloat16* Ph = (__nv_bfloat16*)(sm_ + OPH);
    __nv_bfloat16* Pl = (__nv_bfloat16*)(sm_ + OPL);
    float* ps  = (float*)(sm_ + OPS);
    float* m_s = (float*)(sm_ + OMS);
    float* l_s = (float*)(sm_ + OLS);
    float* a_s = (float*)(sm_ + OAS);

    const int tid = threadIdx.x;
    const int w = tid >> 5, lane = tid & 31;
    const int wm = (w & 1) * 32;          // q rows
    const int wn = (w >> 1) * 16;         // 16-wide n slice
    const int s0 = blockIdx.x * 64;
    const int bh = blockIdx.y;
    const int b = bh >> 3, hh = bh & 7;
    const size_t base = (size_t)b * cS * cD + hh * 64;

    // ldmatrix lane offsets (bytes, stride 144)
    const uint32_t a_lane = (uint32_t)((wm + (lane & 15)) * 144 + (lane >> 4) * 16);
    const uint32_t b_lane = (uint32_t)(
        (wn + ((lane >> 4) & 1) * 8 + (lane & 7)) * 144 + ((lane >> 3) & 1) * 16);

    // load Q tile (split bf16, direct copy); zero tail rows
    #pragma unroll
    for (int u = 0; u < 2; u++) {
        int f = tid + u * 256;
        int r = f >> 3, ch = f & 7;
        uint4 zero = make_uint4(0, 0, 0, 0);
        uint4 hv = zero, lv = zero;
        if (s0 + r < cS) {
            hv = *reinterpret_cast<const uint4*>(qhg + base + (size_t)(s0 + r) * cD + ch * 8);
            lv = *reinterpret_cast<const uint4*>(qlg + base + (size_t)(s0 + r) * cD + ch * 8);
        }
        *reinterpret_cast<uint4*>(Qh + r * AST + ch * 8) = hv;
        *reinterpret_cast<uint4*>(Ql + r * AST + ch * 8) = lv;
    }
    if (tid < 64) { m_s[tid] = -1e30f; l_s[tid] = 0.f; }

    float oacc[2][2][4] = {};

    for (int kb = 0; kb < cS; kb += 64) {
        __syncthreads();
        // K tile: split bf16 direct copy
        #pragma unroll
        for (int u = 0; u < 2; u++) {
            int f = tid + u * 256;
            int r = f >> 3, ch = f & 7;
            uint4 zero = make_uint4(0, 0, 0, 0);
            uint4 hv = zero, lv = zero;
            if (kb + r < cS) {
                hv = *reinterpret_cast<const uint4*>(khg + base + (size_t)(kb + r) * cD + ch * 8);
                lv = *reinterpret_cast<const uint4*>(klg + base + (size_t)(kb + r) * cD + ch * 8);
            }
            *reinterpret_cast<uint4*>(Kh + r * AST + ch * 8) = hv;
            *reinterpret_cast<uint4*>(Kl + r * AST + ch * 8) = lv;
        }
        // V tile: fp32 load, split + transpose store  Vh/Vl[e][key]
        #pragma unroll
        for (int u = 0; u < 4; u++) {
            int f = tid + u * 256;
            int r = f >> 4, c4 = f & 15;
            float4 vv = make_float4(0.f, 0.f, 0.f, 0.f);
            if (kb + r < cS)
                vv = *reinterpret_cast<const float4*>(vg + base + (size_t)(kb + r) * cD + c4 * 4);
            __nv_bfloat16 l0, l1, l2, l3;
            __nv_bfloat16 h0 = __float2bfloat16_rn(vv.x);
            __nv_bfloat16 h1 = __float2bfloat16_rn(vv.y);
            __nv_bfloat16 h2 = __float2bfloat16_rn(vv.z);
            __nv_bfloat16 h3 = __float2bfloat16_rn(vv.w);
            l0 = __float2bfloat16_rn(vv.x - __bfloat162float(h0));
            l1 = __float2bfloat16_rn(vv.y - __bfloat162float(h1));
            l2 = __float2bfloat16_rn(vv.z - __bfloat162float(h2));
            l3 = __float2bfloat16_rn(vv.w - __bfloat162float(h3));
            int e0 = c4 * 4;
            Vh[(e0 + 0) * AST + r] = h0; Vl[(e0 + 0) * AST + r] = l0;
            Vh[(e0 + 1) * AST + r] = h1; Vl[(e0 + 1) * AST + r] = l1;
            Vh[(e0 + 2) * AST + r] = h2; Vl[(e0 + 2) * AST + r] = l2;
            Vh[(e0 + 3) * AST + r] = h3; Vl[(e0 + 3) * AST + r] = l3;
        }
        __syncthreads();

        // ---- S = Q K^T (3-term bf16), accumulate fp32 frags ----
        float scv[2][2][4] = {};
        #pragma unroll
        for (int ks = 0; ks < 4; ks++) {
            const uint32_t kof = (uint32_t)(ks * 32);
            uint32_t qa[2][4], qb[2][4];
            #pragma unroll
            for (int mi = 0; mi < 2; mi++) {
                uint32_t off = a_lane + (uint32_t)(mi * 16 * 144) + kof;
                ldsm4(qa[mi], ub + OQH + off);
                ldsm4(qb[mi], ub + OQL + off);
            }
            uint32_t kh4[4], kl4[4];
            ldsm4(kh4, ub + OKH + b_lane + kof);
            ldsm4(kl4, ub + OKL + b_lane + kof);
            #pragma unroll
            for (int mi = 0; mi < 2; mi++) {
                #pragma unroll
                for (int nh = 0; nh < 2; nh++) {
                    int s = nh * 2;
                    mma16816(scv[mi][nh], qa[mi], kh4[s], kh4[s + 1]);
                    mma16816(scv[mi][nh], qa[mi], kl4[s], kl4[s + 1]);
                    mma16816(scv[mi][nh], qb[mi], kh4[s], kh4[s + 1]);
                }
            }
        }
        // store S to ps (fp32), mask tail cols
        #pragma unroll
        for (int mi = 0; mi < 2; mi++) {
            int r1 = wm + mi * 16 + (lane >> 2);
            int r2 = r1 + 8;
            #pragma unroll
            for (int nh = 0; nh < 2; nh++) {
                int col = wn + nh * 8 + (lane & 3) * 2;
                int g = kb + col;
                float2 v1, v2;
                v1.x = (g     < cS) ? scv[mi][nh][0] : -1e30f;
                v1.y = (g + 1 < cS) ? scv[mi][nh][1] : -1e30f;
                v2.x = (g     < cS) ? scv[mi][nh][2] : -1e30f;
                v2.y = (g + 1 < cS) ? scv[mi][nh][3] : -1e30f;
                *reinterpret_cast<float2*>(&ps[r1 * 68 + col]) = v1;
                *reinterpret_cast<float2*>(&ps[r2 * 68 + col]) = v2;
            }
        }
        __syncthreads();

        // ---- online softmax; write P split bf16 ----
        {
            int row = tid >> 2, qt = tid & 3;
            float* pr = &ps[row * 68 + qt * 16];
            float lm = -1e30f;
            #pragma unroll
            for (int c = 0; c < 16; c++) lm = fmaxf(lm, pr[c]);
            lm = fmaxf(lm, __shfl_xor_sync(0xffffffffu, lm, 1));
            lm = fmaxf(lm, __shfl_xor_sync(0xffffffffu, lm, 2));
            float m_old = m_s[row];
            float m_new = fmaxf(m_old, lm);
            float alpha = __expf(m_old - m_new);
            float lsum = 0.f;
            float pv[16];
            #pragma unroll
            for (int c = 0; c < 16; c++) {
                float p = __expf(pr[c] - m_new);
                pv[c] = p;
                lsum += p;
            }
            lsum += __shfl_xor_sync(0xffffffffu, lsum, 1);
            lsum += __shfl_xor_sync(0xffffffffu, lsum, 2);
            int cbase = row * AST + qt * 16;
            #pragma unroll
            for (int c = 0; c < 16; c += 2) {
                __nv_bfloat16 lx, ly;
                uint32_t hp = pack_split(pv[c], pv[c + 1], lx, ly);
                __nv_bfloat162 lp(lx, ly);
                *reinterpret_cast<uint32_t*>(Ph + cbase + c) = hp;
                *reinterpret_cast<uint32_t*>(Pl + cbase + c) =
                    *reinterpret_cast<uint32_t*>(&lp);
            }
            if (qt == 0) {
                m_s[row] = m_new;
                l_s[row] = l_s[row] * alpha + lsum;
                a_s[row] = alpha;
            }
        }
        __syncthreads();

        // rescale O by alpha
        #pragma unroll
        for (int mi = 0; mi < 2; mi++) {
            float al1 = a_s[wm + mi * 16 + (lane >> 2)];
            float al2 = a_s[wm + mi * 16 + (lane >> 2) + 8];
            #pragma unroll
            for (int nh = 0; nh < 2; nh++) {
                oacc[mi][nh][0] *= al1; oacc[mi][nh][1] *= al1;
                oacc[mi][nh][2] *= al2; oacc[mi][nh][3] *= al2;
            }
        }

        // ---- O += P V (3-term bf16) ----
        #pragma unroll
        for (int ks = 0; ks < 4; ks++) {
            const uint32_t kof = (uint32_t)(ks * 32);
            uint32_t pa[2][4], pb[2][4];
            #pragma unroll
            for (int mi = 0; mi < 2; mi++) {
                uint32_t off = a_lane + (uint32_t)(mi * 16 * 144) + kof;
                ldsm4(pa[mi], ub + OPH + off);
                ldsm4(pb[mi], ub + OPL + off);
            }
            uint32_t vh4[4], vl4[4];
            ldsm4(vh4, ub + OVH + b_lane + kof);
            ldsm4(vl4, ub + OVL + b_lane + kof);
            #pragma unroll
            for (int mi = 0; mi < 2; mi++) {
                #pragma unroll
                for (int nh = 0; nh < 2; nh++) {
                    int s = nh * 2;
                    mma16816(oacc[mi][nh], pa[mi], vh4[s], vh4[s + 1]);
                    mma16816(oacc[mi][nh], pa[mi], vl4[s], vl4[s + 1]);
                    mma16816(oacc[mi][nh], pb[mi], vh4[s], vh4[s + 1]);
                }
            }
        }
    }
    __syncthreads();

    // final: scale by 1/l, split-write o
    #pragma unroll
    for (int mi = 0; mi < 2; mi++) {
        int rr1 = wm + mi * 16 + (lane >> 2);
        int rr2 = rr1 + 8;
        float inv1 = 1.f / l_s[rr1];
        float inv2 = 1.f / l_s[rr2];
        #pragma unroll
        for (int nh = 0; nh < 2; nh++) {
            int col = wn + nh * 8 + (lane & 3) * 2;
            int s1 = s0 + rr1, s2 = s0 + rr2;
            if (s1 < cS) {
                __nv_bfloat16 lx, ly;
                uint32_t hp = pack_split(oacc[mi][nh][0] * inv1, oacc[mi][nh][1] * inv1, lx, ly);
                __nv_bfloat162 lp(lx, ly);
                size_t off = base + (size_t)s1 * cD + col;
                *reinterpret_cast<uint32_t*>(oh + off) = hp;
                *reinterpret_cast<uint32_t*>(ol + off) = *reinterpret_cast<uint32_t*>(&lp);
            }
            if (s2 < cS) {
                __nv_bfloat16 lx, ly;
                uint32_t hp = pack_split(oacc[mi][nh][2] * inv2, oacc[mi][nh][3] * inv2, lx, ly);
                __nv_bfloat162 lp(lx, ly);
                size_t off = base + (size_t)s2 * cD + col;
                *reinterpret_cast<uint32_t*>(oh + off) = hp;
                *reinterpret_cast<uint32_t*>(ol + off) = *reinterpret_cast<uint32_t*>(&lp);
            }
        }
    }
}

// ---------------- LayerNorm over rows of 512 (optional split output) --------
template<bool SPLIT>
__global__ void k_ln(const float* __restrict__ x, const float* __restrict__ w,
                     const float* __restrict__ bb, float* __restrict__ out,
                     __nv_bfloat16* __restrict__ oh, __nv_bfloat16* __restrict__ ol)
{
    __shared__ float red[4];
    int row = blockIdx.x;
    int t = threadIdx.x;
    const float4 v = reinterpret_cast<const float4*>(x + (size_t)row * cD)[t];
    float s = v.x + v.y + v.z + v.w;
    #pragma unroll
    for (int o = 16; o > 0; o >>= 1) s += __shfl_xor_sync(0xffffffffu, s, o);
    if ((t & 31) == 0) red[t >> 5] = s;
    __syncthreads();
    float mean = (red[0] + red[1] + red[2] + red[3]) * (1.0f / cD);
    float dx = v.x - mean, dy = v.y - mean, dz = v.z - mean, dw = v.w - mean;
    float s2 = dx * dx + dy * dy + dz * dz + dw * dw;
    #pragma unroll
    for (int o = 16; o > 0; o >>= 1) s2 += __shfl_xor_sync(0xffffffffu, s2, o);
    __syncthreads();
    if ((t & 31) == 0) red[t >> 5] = s2;
    __syncthreads();
    float var = (red[0] + red[1] + red[2] + red[3]) * (1.0f / cD);
    float inv = rsqrtf(var + 1e-5f);
    float4 wv = reinterpret_cast<const float4*>(w)[t];
    float4 bv = reinterpret_cast<const float4*>(bb)[t];
    float4 r4;
    r4.x = dx * inv * wv.x + bv.x;
    r4.y = dy * inv * wv.y + bv.y;
    r4.z = dz * inv * wv.z + bv.z;
    r4.w = dw * inv * wv.w + bv.w;
    reinterpret_cast<float4*>(out + (size_t)row * cD)[t] = r4;
    if (SPLIT) {
        size_t off = (size_t)row * cD + t * 4;
        __nv_bfloat16 lx, ly;
        uint32_t h01 = pack_split(r4.x, r4.y, lx, ly);
        __nv_bfloat162 lo01(lx, ly);
        uint32_t h23 = pack_split(r4.z, r4.w, lx, ly);
        __nv_bfloat162 lo23(lx, ly);
        *reinterpret_cast<uint2*>(oh + off) = make_uint2(h01, h23);
        *reinterpret_cast<uint2*>(ol + off) =
            make_uint2(*reinterpret_cast<uint32_t*>(&lo01),
                       *reinterpret_cast<uint32_t*>(&lo23));
    }
}

// ---------------- driver ----------------
extern "C" void kernel_launch(void* const* d_in, const int* in_sizes, int n_in,
                              void* d_out, int out_size)
{
    const int*   x    = (const int*)  d_in[0];
    const float* emb  = (const float*)d_in[1];
    const float* pe   = (const float*)d_in[2];
    const float* Wq   = (const float*)d_in[3];
    const float* Wk   = (const float*)d_in[4];
    const float* Wv   = (const float*)d_in[5];
    const float* Wo   = (const float*)d_in[6];
    const float* bo   = (const float*)d_in[7];
    const float* ln1w = (const float*)d_in[8];
    const float* ln1b = (const float*)d_in[9];
    const float* W1   = (const float*)d_in[10];
    const float* b1   = (const float*)d_in[11];
    const float* W2   = (const float*)d_in[12];
    const float* b2   = (const float*)d_in[13];
    const float* ln2w = (const float*)d_in[14];
    const float* ln2b = (const float*)d_in[15];
    float* out = (float*)d_out;

    float *h, *v, *t, *n1, *t2;
    __nv_bfloat16 *qh, *ql, *kh, *kl, *ah, *al, *fh, *fl, *wh, *wl;
    cudaGetSymbolAddress((void**)&h,  g_h);
    cudaGetSymbolAddress((void**)&v,  g_v);
    cudaGetSymbolAddress((void**)&t,  g_t);
    cudaGetSymbolAddress((void**)&n1, g_n1);
    cudaGetSymbolAddress((void**)&t2, g_t2);
    cudaGetSymbolAddress((void**)&qh, g_qh);
    cudaGetSymbolAddress((void**)&ql, g_ql);
    cudaGetSymbolAddress((void**)&kh, g_kh);
    cudaGetSymbolAddress((void**)&kl, g_kl);
    cudaGetSymbolAddress((void**)&ah, g_ah);
    cudaGetSymbolAddress((void**)&al, g_al);
    cudaGetSymbolAddress((void**)&fh, g_fh);
    cudaGetSymbolAddress((void**)&fl, g_fl);
    cudaGetSymbolAddress((void**)&wh, g_wh);
    cudaGetSymbolAddress((void**)&wl, g_wl);

    cudaFuncSetAttribute(k_attn, cudaFuncAttributeMaxDynamicSharedMemorySize, ATTN_SMEM_BYTES);
    cudaFuncSetAttribute(mma_gemm<0>, cudaFuncAttributeMaxDynamicSharedMemorySize, GEMM_SMEM);
    cudaFuncSetAttribute(mma_gemm<1>, cudaFuncAttributeMaxDynamicSharedMemorySize, GEMM_SMEM);

    k_embed<<<(cBS * cD / 4 + 255) / 256, 256>>>(x, emb, pe, h);

    for (int l = 0; l < cL; l++) {
        k_qkv<<<cBSH / 64, 256>>>(h, Wq + l * cHD * cHD, Wk + l * cHD * cHD,
                                  Wv + l * cHD * cHD, qh, ql, kh, kl, v);
        // attention -> o (split bf16 in ah/al)
        k_attn<<<dim3((cS + 63) / 64, cB * cH), 256, ATTN_SMEM_BYTES>>>(
            qh, ql, kh, kl, v, ah, al);

        // t = o @ Wo^T + bo + h
        k_split<<<(cD * cD / 4 + 255) / 256, 256>>>(Wo + (size_t)l * cD * cD, wh, wl, cD * cD / 4);
        mma_gemm<0><<<dim3(cD / 64, cBS / 128), 256, GEMM_SMEM>>>(
            ah, al, wh, wl, bo + l * cD, h, t, nullptr, nullptr, cBS, cD, cD);
        k_ln<true><<<cBS, 128>>>(t, ln1w + l * cD, ln1b + l * cD, n1, ah, al);

        // f1 = relu(n1 @ W1^T + b1)  (split bf16 out)
        k_split<<<(cF * cD / 4 + 255) / 256, 256>>>(W1 + (size_t)l * cF * cD, wh, wl, cF * cD / 4);
        mma_gemm<1><<<dim3(cF / 64, cBS / 128), 256, GEMM_SMEM>>>(
            ah, al, wh, wl, b1 + l * cF, nullptr, nullptr, fh, fl, cBS, cF, cD);

        // t2 = f1 @ W2^T + b2 + n1
        k_split<<<(cF * cD / 4 + 255) / 256, 256>>>(W2 + (size_t)l * cD * cF, wh, wl, cF * cD / 4);
        mma_gemm<0><<<dim3(cD / 64, cBS / 128), 256, GEMM_SMEM>>>(
            fh, fl, wh, wl, b2 + l * cD, n1, t2, nullptr, nullptr, cBS, cD, cF);

        k_ln<false><<<cBS, 128>>>(t2, ln2w + l * cD, ln2b + l * cD,
                                  (l == cL - 1) ? out : h, nullptr, nullptr);
    }
}